// round 8
// baseline (speedup 1.0000x reference)
#include <cuda_runtime.h>
#include <cuda_bf16.h>
#include <cstdint>

#define NN 100000
#define EE 1600000
#define DD 128
#define HH 128

// ---------------------------------------------------------------------------
// Scratch
// ---------------------------------------------------------------------------
__device__ float4 g_s4[NN][DD / 4];          // normalized neighbor means (one relation)
__device__ int    g_cnt[NN];                 // histogram
__device__ int    g_rs[NN + 1];              // CSR row_start
__device__ int    g_cur[NN];                 // fill cursors
__device__ int    g_srcp[EE];                // permuted src
__device__ float  g_wp[EE];                  // permuted w
// B^T = [Ws;Wn]^T in [n][k] layout (128 x 256), bf16 hi/lo split.
__device__ __nv_bfloat16 g_Bhi[128 * 256];
__device__ __nv_bfloat16 g_Blo[128 * 256];

// ---------------------------------------------------------------------------
// CSR build
// ---------------------------------------------------------------------------
__global__ void zero_cnt_kernel() {
    int i = blockIdx.x * blockDim.x + threadIdx.x;
    if (i < NN) g_cnt[i] = 0;
}

__global__ void hist_kernel(const int* __restrict__ dst) {
    int e = blockIdx.x * blockDim.x + threadIdx.x;
    if (e < EE) atomicAdd(&g_cnt[__ldg(&dst[e])], 1);
}

// Single-block chunked exclusive scan of g_cnt -> g_rs (+ copy to g_cur).
__global__ void scan_kernel() {
    __shared__ int part[1024];
    int t = threadIdx.x;
    const int CH = (NN + 1023) / 1024;       // 98
    int beg = t * CH;
    int end = min(beg + CH, NN);
    int s = 0;
    for (int i = beg; i < end; i++) s += g_cnt[i];
    part[t] = s;
    __syncthreads();
    for (int off = 1; off < 1024; off <<= 1) {
        int v = part[t];
        int u = (t >= off) ? part[t - off] : 0;
        __syncthreads();
        part[t] = v + u;
        __syncthreads();
    }
    int pre = (t > 0) ? part[t - 1] : 0;
    for (int i = beg; i < end; i++) {
        g_rs[i] = pre;
        g_cur[i] = pre;
        pre += g_cnt[i];
    }
    if (t == 1023) g_rs[NN] = pre;
}

__global__ void fill_kernel(const int* __restrict__ src, const int* __restrict__ dst,
                            const float* __restrict__ w) {
    int e = blockIdx.x * blockDim.x + threadIdx.x;
    if (e >= EE) return;
    int v = __ldg(&dst[e]);
    int pos = atomicAdd(&g_cur[v], 1);
    g_srcp[pos] = __ldg(&src[e]);
    g_wp[pos]   = __ldg(&w[e]);
}

// ---------------------------------------------------------------------------
// Pull: one warp per dst node. Gather x[src] rows (coalesced 512B), FMA into
// registers, single pre-normalized store. No atomics, no zero-fill needed.
// ---------------------------------------------------------------------------
__global__ __launch_bounds__(256) void pull_kernel(const float* __restrict__ x) {
    int v = (int)((blockIdx.x * blockDim.x + threadIdx.x) >> 5);
    if (v >= NN) return;
    int lane = threadIdx.x & 31;

    int beg = __ldg(&g_rs[v]);
    int end = __ldg(&g_rs[v + 1]);

    float4 acc = make_float4(0.f, 0.f, 0.f, 0.f);
    int e = beg;
    // unroll-by-2 for MLP
    for (; e + 2 <= end; e += 2) {
        int   u0 = __ldg(&g_srcp[e]),     u1 = __ldg(&g_srcp[e + 1]);
        float w0 = __ldg(&g_wp[e]),       w1 = __ldg(&g_wp[e + 1]);
        float4 a = __ldg(((const float4*)x) + (size_t)u0 * 32 + lane);
        float4 b = __ldg(((const float4*)x) + (size_t)u1 * 32 + lane);
        acc.x += w0 * a.x + w1 * b.x;
        acc.y += w0 * a.y + w1 * b.y;
        acc.z += w0 * a.z + w1 * b.z;
        acc.w += w0 * a.w + w1 * b.w;
    }
    if (e < end) {
        int   u0 = __ldg(&g_srcp[e]);
        float w0 = __ldg(&g_wp[e]);
        float4 a = __ldg(((const float4*)x) + (size_t)u0 * 32 + lane);
        acc.x += w0 * a.x; acc.y += w0 * a.y;
        acc.z += w0 * a.z; acc.w += w0 * a.w;
    }
    float inv = 1.0f / fmaxf((float)(end - beg), 1.0f);
    g_s4[v][lane] = make_float4(acc.x * inv, acc.y * inv, acc.z * inv, acc.w * inv);
}

// ---------------------------------------------------------------------------
// B pre-convert: g_Bhi/g_Blo[n][k] = hi/lo(W[k][n]), W = [Ws;Wn]
// ---------------------------------------------------------------------------
__global__ void bconv_kernel(const float* __restrict__ Ws, const float* __restrict__ Wn) {
    int k = blockIdx.x;      // 0..255
    int n = threadIdx.x;     // 0..127
    float wv = (k < 128) ? __ldg(&Ws[k * 128 + n]) : __ldg(&Wn[(k - 128) * 128 + n]);
    __nv_bfloat16 h = __float2bfloat16(wv);
    __nv_bfloat16 l = __float2bfloat16(wv - __bfloat162float(h));
    g_Bhi[n * 256 + k] = h;
    g_Blo[n * 256 + k] = l;
}

// ---------------------------------------------------------------------------
// PTX helpers: ldmatrix + bf16 mma (baseline sm_80+ features, OK for sm_103)
// ---------------------------------------------------------------------------
__device__ __forceinline__ uint32_t smem_u32(const void* p) {
    uint32_t a;
    asm("{ .reg .u64 t; cvta.to.shared.u64 t, %1; cvt.u32.u64 %0, t; }"
        : "=r"(a) : "l"(p));
    return a;
}
#define LDSM_X4(r0, r1, r2, r3, addr) \
    asm volatile("ldmatrix.sync.aligned.m8n8.x4.shared.b16 {%0,%1,%2,%3}, [%4];" \
        : "=r"(r0), "=r"(r1), "=r"(r2), "=r"(r3) : "r"(addr))
#define LDSM_X2(r0, r1, addr) \
    asm volatile("ldmatrix.sync.aligned.m8n8.x2.shared.b16 {%0,%1}, [%2];" \
        : "=r"(r0), "=r"(r1) : "r"(addr))
#define MMA_BF16(d, a, b) \
    asm volatile("mma.sync.aligned.m16n8k16.row.col.f32.bf16.bf16.f32 " \
        "{%0,%1,%2,%3}, {%4,%5,%6,%7}, {%8,%9}, {%0,%1,%2,%3};" \
        : "+f"((d)[0]), "+f"((d)[1]), "+f"((d)[2]), "+f"((d)[3]) \
        : "r"((a)[0]), "r"((a)[1]), "r"((a)[2]), "r"((a)[3]), \
          "r"((b)[0]), "r"((b)[1]))

#define ASTR 40   // smem row stride (b16): conflict-free ldmatrix phases

// ---------------------------------------------------------------------------
// Tensor-core GEMM (mma.sync bf16, 3-pass hi/lo split), one relation:
//   z = [x | s] @ [Ws;Wn] + b ;  out (+)= relu(z)/3     (s pre-normalized)
// CTA 128x128, 8 warps (4M x 2N), warp tile 32x64. K chunks of 32.
// ---------------------------------------------------------------------------
__global__ __launch_bounds__(256, 2) void gemm_mma_kernel(
    const float* __restrict__ x, const float* __restrict__ bias,
    float* __restrict__ out, int first)
{
    __shared__ __align__(16) __nv_bfloat16 sAhi[128][ASTR];
    __shared__ __align__(16) __nv_bfloat16 sAlo[128][ASTR];
    __shared__ __align__(16) __nv_bfloat16 sBhi[128][ASTR];
    __shared__ __align__(16) __nv_bfloat16 sBlo[128][ASTR];

    int tid = threadIdx.x;
    int wid = tid >> 5, lid = tid & 31;
    int m0  = blockIdx.x * 128;

    int wm = wid & 3;        // M quadrant: rows wm*32 .. +31
    int wn = wid >> 2;       // N half:    cols wn*64 .. +63

    float acc[2][8][4];
    #pragma unroll
    for (int i = 0; i < 2; i++)
        #pragma unroll
        for (int j = 0; j < 8; j++)
            #pragma unroll
            for (int q = 0; q < 4; q++) acc[i][j][q] = 0.f;

    uint32_t aHiBase = smem_u32(&sAhi[0][0]);
    uint32_t aLoBase = smem_u32(&sAlo[0][0]);
    uint32_t bHiBase = smem_u32(&sBhi[0][0]);
    uint32_t bLoBase = smem_u32(&sBlo[0][0]);

    int aRow = lid & 15;
    int aKof = (lid >> 4) * 8;
    int bRow = lid & 7;
    int bKof = ((lid >> 3) & 1) * 8;

    for (int c = 0; c < 8; c++) {
        // ---- stage A chunk (128 rows x 32 k) as bf16 hi/lo
        #pragma unroll
        for (int h = 0; h < 4; h++) {
            int f   = tid + h * 256;      // 0..1023
            int row = f >> 3;
            int kq  = f & 7;
            int m   = m0 + row;
            float4 v = make_float4(0.f, 0.f, 0.f, 0.f);
            if (m < NN) {
                if (c < 4) v = __ldg((const float4*)(x + (size_t)m * 128 + c * 32) + kq);
                else       v = __ldg((const float4*)&g_s4[m][0] + (c - 4) * 8 + kq);
            }
            __nv_bfloat16 h0 = __float2bfloat16(v.x), h1 = __float2bfloat16(v.y);
            __nv_bfloat16 h2 = __float2bfloat16(v.z), h3 = __float2bfloat16(v.w);
            __nv_bfloat16 l0 = __float2bfloat16(v.x - __bfloat162float(h0));
            __nv_bfloat16 l1 = __float2bfloat16(v.y - __bfloat162float(h1));
            __nv_bfloat16 l2 = __float2bfloat16(v.z - __bfloat162float(h2));
            __nv_bfloat16 l3 = __float2bfloat16(v.w - __bfloat162float(h3));
            uint32_t hp0 = (uint32_t)__bfloat16_as_ushort(h0) |
                           ((uint32_t)__bfloat16_as_ushort(h1) << 16);
            uint32_t hp1 = (uint32_t)__bfloat16_as_ushort(h2) |
                           ((uint32_t)__bfloat16_as_ushort(h3) << 16);
            uint32_t lp0 = (uint32_t)__bfloat16_as_ushort(l0) |
                           ((uint32_t)__bfloat16_as_ushort(l1) << 16);
            uint32_t lp1 = (uint32_t)__bfloat16_as_ushort(l2) |
                           ((uint32_t)__bfloat16_as_ushort(l3) << 16);
            *(uint2*)&sAhi[row][kq * 4] = make_uint2(hp0, hp1);
            *(uint2*)&sAlo[row][kq * 4] = make_uint2(lp0, lp1);
        }
        // ---- stage B chunk (128 n x 32 k) from pre-split global
        #pragma unroll
        for (int h = 0; h < 2; h++) {
            int f  = tid + h * 256;
            int n  = f >> 2;
            int kq = f & 3;
            const float4* sh = (const float4*)(g_Bhi + n * 256 + c * 32) + kq;
            const float4* sl = (const float4*)(g_Blo + n * 256 + c * 32) + kq;
            *(float4*)&sBhi[n][kq * 8] = __ldg(sh);
            *(float4*)&sBlo[n][kq * 8] = __ldg(sl);
        }
        __syncthreads();

        #pragma unroll
        for (int ks = 0; ks < 2; ks++) {
            uint32_t ahi[2][4], alo[2][4];
            #pragma unroll
            for (int mt = 0; mt < 2; mt++) {
                uint32_t off = (uint32_t)(((wm * 32 + mt * 16 + aRow) * ASTR
                                           + ks * 16 + aKof) * 2);
                LDSM_X4(ahi[mt][0], ahi[mt][1], ahi[mt][2], ahi[mt][3], aHiBase + off);
                LDSM_X4(alo[mt][0], alo[mt][1], alo[mt][2], alo[mt][3], aLoBase + off);
            }
            #pragma unroll
            for (int nt = 0; nt < 8; nt++) {
                uint32_t bo = (uint32_t)(((wn * 64 + nt * 8 + bRow) * ASTR
                                          + ks * 16 + bKof) * 2);
                uint32_t bhi[2], blo[2];
                LDSM_X2(bhi[0], bhi[1], bHiBase + bo);
                LDSM_X2(blo[0], blo[1], bLoBase + bo);
                #pragma unroll
                for (int mt = 0; mt < 2; mt++) {
                    MMA_BF16(acc[mt][nt], ahi[mt], bhi);
                    MMA_BF16(acc[mt][nt], alo[mt], bhi);
                    MMA_BF16(acc[mt][nt], ahi[mt], blo);
                }
            }
        }
        __syncthreads();
    }

    // ---- epilogue: bias + relu, scale 1/3, RMW out
    const float third = 1.0f / 3.0f;
    int tq = lid >> 2;
    int tr = lid & 3;
    #pragma unroll
    for (int mt = 0; mt < 2; mt++) {
        int rbase = m0 + wm * 32 + mt * 16 + tq;
        #pragma unroll
        for (int hf = 0; hf < 2; hf++) {
            int row = rbase + hf * 8;
            if (row >= NN) continue;
            float* op = out + (size_t)row * 128;
            #pragma unroll
            for (int nt = 0; nt < 8; nt++) {
                int col = wn * 64 + nt * 8 + tr * 2;
                float v0 = acc[mt][nt][hf * 2 + 0] + __ldg(&bias[col]);
                float v1 = acc[mt][nt][hf * 2 + 1] + __ldg(&bias[col + 1]);
                v0 = fmaxf(v0, 0.f) * third;
                v1 = fmaxf(v1, 0.f) * third;
                if (!first) {
                    float2 o = *(const float2*)(op + col);
                    v0 += o.x; v1 += o.y;
                }
                *(float2*)(op + col) = make_float2(v0, v1);
            }
        }
    }
}

// ---------------------------------------------------------------------------
// Launch. Inputs identified BY SIZE (robust to either metadata ordering).
// ---------------------------------------------------------------------------
extern "C" void kernel_launch(void* const* d_in, const int* in_sizes, int n_in,
                              void* d_out, int out_size)
{
    const float* x = nullptr;
    const int*   srcA[3] = {nullptr, nullptr, nullptr};
    const int*   dstA[3] = {nullptr, nullptr, nullptr};
    const float* wA[3]   = {nullptr, nullptr, nullptr};
    const float* WsA[3]  = {nullptr, nullptr, nullptr};
    const float* WnA[3]  = {nullptr, nullptr, nullptr};
    const float* bA[3]   = {nullptr, nullptr, nullptr};

    int nEdge = 0, nMat = 0, nBias = 0;
    for (int i = 0; i < n_in; i++) {
        int sz = in_sizes[i];
        if (sz == NN * DD) {
            x = (const float*)d_in[i];
        } else if (sz == EE) {
            int k = nEdge++;
            int rel = k / 3, kind = k % 3;
            if (rel < 3) {
                if (kind == 0)      srcA[rel] = (const int*)d_in[i];
                else if (kind == 1) dstA[rel] = (const int*)d_in[i];
                else                wA[rel]   = (const float*)d_in[i];
            }
        } else if (sz == DD * HH) {
            int k = nMat++;
            int rel = k / 2;
            if (rel < 3) {
                if ((k & 1) == 0) WsA[rel] = (const float*)d_in[i];
                else              WnA[rel] = (const float*)d_in[i];
            }
        } else if (sz == HH) {
            if (nBias < 3) bA[nBias++] = (const float*)d_in[i];
        }
    }

    float* out = (float*)d_out;

    int edgeBlocks = (EE + 255) / 256;       // 6250
    int nodeBlocks = (NN + 255) / 256;       // 391
    int pullBlocks = (NN * 32 + 255) / 256;  // 12500
    int gemmBlocks = (NN + 127) / 128;       // 782

    for (int r = 0; r < 3; r++) {
        zero_cnt_kernel<<<nodeBlocks, 256>>>();
        hist_kernel<<<edgeBlocks, 256>>>(dstA[r]);
        scan_kernel<<<1, 1024>>>();
        fill_kernel<<<edgeBlocks, 256>>>(srcA[r], dstA[r], wA[r]);
        pull_kernel<<<pullBlocks, 256>>>(x);
        bconv_kernel<<<256, 128>>>(WsA[r], WnA[r]);
        gemm_mma_kernel<<<gemmBlocks, 256>>>(x, bA[r], out, r == 0);
    }
}

// round 9
// speedup vs baseline: 1.7922x; 1.7922x over previous
#include <cuda_runtime.h>
#include <cuda_bf16.h>
#include <cstdint>

#define NN 100000
#define EE 1600000
#define DD 128
#define HH 128

// ---------------------------------------------------------------------------
// Scratch
// ---------------------------------------------------------------------------
__device__ float4 g_s4[NN][DD / 4];          // normalized neighbor means (one relation)
__device__ int    g_cnt[NN];                 // in-degree histogram
__device__ int    g_rs[NN + 1];              // CSR row_start
__device__ int    g_cur[NN];                 // fill cursors
__device__ int2   g_pair[EE];                // (src, w-as-int) permuted by dst
__device__ int    g_partraw[128];            // block partial sums
__device__ int    g_part[128];               // scanned partials
// B^T = [Ws;Wn]^T in [n][k] layout (128 x 256), bf16 hi/lo split.
__device__ __nv_bfloat16 g_Bhi[128 * 256];
__device__ __nv_bfloat16 g_Blo[128 * 256];

#define SCAN_B 98          // ceil(NN / 1024)

// ---------------------------------------------------------------------------
// CSR build
// ---------------------------------------------------------------------------
__global__ void zero_cnt_kernel() {
    int i = blockIdx.x * blockDim.x + threadIdx.x;
    if (i < NN) g_cnt[i] = 0;
}

__global__ void hist_kernel(const int* __restrict__ dst) {
    int e = blockIdx.x * blockDim.x + threadIdx.x;
    if (e < EE) atomicAdd(&g_cnt[__ldg(&dst[e])], 1);
}

// k1: per-1024-block reduction of g_cnt -> g_partraw
__global__ void scan_reduce_kernel() {
    int b = blockIdx.x, t = threadIdx.x;
    int gi = b * 1024 + t;
    int v = (gi < NN) ? g_cnt[gi] : 0;
    // warp reduce
    #pragma unroll
    for (int o = 16; o > 0; o >>= 1) v += __shfl_down_sync(0xFFFFFFFFu, v, o);
    __shared__ int wsum[32];
    int lane = t & 31, wid = t >> 5;
    if (lane == 0) wsum[wid] = v;
    __syncthreads();
    if (wid == 0) {
        int s = wsum[lane];
        #pragma unroll
        for (int o = 16; o > 0; o >>= 1) s += __shfl_down_sync(0xFFFFFFFFu, s, o);
        if (lane == 0) g_partraw[b] = s;
    }
}

// k2: tiny exclusive scan of SCAN_B partials
__global__ void scan_part_kernel() {
    __shared__ int sm[SCAN_B];
    int t = threadIdx.x;
    if (t < SCAN_B) sm[t] = g_partraw[t];
    __syncthreads();
    if (t == 0) {
        int run = 0;
        for (int i = 0; i < SCAN_B; i++) { int c = sm[i]; sm[i] = run; run += c; }
    }
    __syncthreads();
    if (t < SCAN_B) g_part[t] = sm[t];
}

// k3: distributed block-level exclusive scan + base -> g_rs, g_cur
__global__ void scan_final_kernel() {
    int b = blockIdx.x, t = threadIdx.x;
    int gi = b * 1024 + t;
    int lane = t & 31, wid = t >> 5;
    int v = (gi < NN) ? g_cnt[gi] : 0;
    int xv = v;
    #pragma unroll
    for (int o = 1; o < 32; o <<= 1) {
        int y = __shfl_up_sync(0xFFFFFFFFu, xv, o);
        if (lane >= o) xv += y;
    }
    __shared__ int wsum[32];
    if (lane == 31) wsum[wid] = xv;
    __syncthreads();
    if (wid == 0) {
        int s = wsum[lane];
        #pragma unroll
        for (int o = 1; o < 32; o <<= 1) {
            int y = __shfl_up_sync(0xFFFFFFFFu, s, o);
            if (lane >= o) s += y;
        }
        wsum[lane] = s;
    }
    __syncthreads();
    int excl = xv - v + ((wid > 0) ? wsum[wid - 1] : 0) + g_part[b];
    if (gi < NN) { g_rs[gi] = excl; g_cur[gi] = excl; }
    if (gi == NN - 1) g_rs[NN] = excl + v;
}

__global__ void fill_kernel(const int* __restrict__ src, const int* __restrict__ dst,
                            const float* __restrict__ w) {
    int e = blockIdx.x * blockDim.x + threadIdx.x;
    if (e >= EE) return;
    int v = __ldg(&dst[e]);
    int pos = atomicAdd(&g_cur[v], 1);
    g_pair[pos] = make_int2(__ldg(&src[e]), __float_as_int(__ldg(&w[e])));
}

// ---------------------------------------------------------------------------
// Pull: one warp per dst node, unroll-4 for MLP. No atomics. Pre-normalized.
// ---------------------------------------------------------------------------
__global__ __launch_bounds__(256) void pull_kernel(const float* __restrict__ x) {
    int v = (int)((blockIdx.x * blockDim.x + threadIdx.x) >> 5);
    if (v >= NN) return;
    int lane = threadIdx.x & 31;

    int beg = __ldg(&g_rs[v]);
    int end = __ldg(&g_rs[v + 1]);
    const float4* x4 = (const float4*)x;

    float4 acc = make_float4(0.f, 0.f, 0.f, 0.f);
    int e = beg;
    for (; e + 4 <= end; e += 4) {
        int2 p0 = __ldg(&g_pair[e]);
        int2 p1 = __ldg(&g_pair[e + 1]);
        int2 p2 = __ldg(&g_pair[e + 2]);
        int2 p3 = __ldg(&g_pair[e + 3]);
        float4 a0 = __ldg(x4 + (size_t)p0.x * 32 + lane);
        float4 a1 = __ldg(x4 + (size_t)p1.x * 32 + lane);
        float4 a2 = __ldg(x4 + (size_t)p2.x * 32 + lane);
        float4 a3 = __ldg(x4 + (size_t)p3.x * 32 + lane);
        float w0 = __int_as_float(p0.y), w1 = __int_as_float(p1.y);
        float w2 = __int_as_float(p2.y), w3 = __int_as_float(p3.y);
        acc.x += w0 * a0.x + w1 * a1.x + w2 * a2.x + w3 * a3.x;
        acc.y += w0 * a0.y + w1 * a1.y + w2 * a2.y + w3 * a3.y;
        acc.z += w0 * a0.z + w1 * a1.z + w2 * a2.z + w3 * a3.z;
        acc.w += w0 * a0.w + w1 * a1.w + w2 * a2.w + w3 * a3.w;
    }
    for (; e < end; e++) {
        int2 p = __ldg(&g_pair[e]);
        float4 a = __ldg(x4 + (size_t)p.x * 32 + lane);
        float ww = __int_as_float(p.y);
        acc.x += ww * a.x; acc.y += ww * a.y;
        acc.z += ww * a.z; acc.w += ww * a.w;
    }
    float inv = 1.0f / fmaxf((float)(end - beg), 1.0f);
    g_s4[v][lane] = make_float4(acc.x * inv, acc.y * inv, acc.z * inv, acc.w * inv);
}

// ---------------------------------------------------------------------------
// B pre-convert: g_Bhi/g_Blo[n][k] = hi/lo(W[k][n]), W = [Ws;Wn]
// ---------------------------------------------------------------------------
__global__ void bconv_kernel(const float* __restrict__ Ws, const float* __restrict__ Wn) {
    int k = blockIdx.x;      // 0..255
    int n = threadIdx.x;     // 0..127
    float wv = (k < 128) ? __ldg(&Ws[k * 128 + n]) : __ldg(&Wn[(k - 128) * 128 + n]);
    __nv_bfloat16 h = __float2bfloat16(wv);
    __nv_bfloat16 l = __float2bfloat16(wv - __bfloat162float(h));
    g_Bhi[n * 256 + k] = h;
    g_Blo[n * 256 + k] = l;
}

// ---------------------------------------------------------------------------
// PTX helpers: ldmatrix + bf16 mma (baseline sm_80+ features, OK for sm_103)
// ---------------------------------------------------------------------------
__device__ __forceinline__ uint32_t smem_u32(const void* p) {
    uint32_t a;
    asm("{ .reg .u64 t; cvta.to.shared.u64 t, %1; cvt.u32.u64 %0, t; }"
        : "=r"(a) : "l"(p));
    return a;
}
#define LDSM_X4(r0, r1, r2, r3, addr) \
    asm volatile("ldmatrix.sync.aligned.m8n8.x4.shared.b16 {%0,%1,%2,%3}, [%4];" \
        : "=r"(r0), "=r"(r1), "=r"(r2), "=r"(r3) : "r"(addr))
#define LDSM_X2(r0, r1, addr) \
    asm volatile("ldmatrix.sync.aligned.m8n8.x2.shared.b16 {%0,%1}, [%2];" \
        : "=r"(r0), "=r"(r1) : "r"(addr))
#define MMA_BF16(d, a, b) \
    asm volatile("mma.sync.aligned.m16n8k16.row.col.f32.bf16.bf16.f32 " \
        "{%0,%1,%2,%3}, {%4,%5,%6,%7}, {%8,%9}, {%0,%1,%2,%3};" \
        : "+f"((d)[0]), "+f"((d)[1]), "+f"((d)[2]), "+f"((d)[3]) \
        : "r"((a)[0]), "r"((a)[1]), "r"((a)[2]), "r"((a)[3]), \
          "r"((b)[0]), "r"((b)[1]))

#define ASTR 40   // smem row stride (b16): conflict-free ldmatrix phases

// ---------------------------------------------------------------------------
// Tensor-core GEMM (mma.sync bf16, 3-pass hi/lo split), one relation:
//   z = [x | s] @ [Ws;Wn] + b ;  out (+)= relu(z)/3     (s pre-normalized)
// CTA 128x128, 8 warps (4M x 2N), warp tile 32x64. K chunks of 32.
// ---------------------------------------------------------------------------
__global__ __launch_bounds__(256, 2) void gemm_mma_kernel(
    const float* __restrict__ x, const float* __restrict__ bias,
    float* __restrict__ out, int first)
{
    __shared__ __align__(16) __nv_bfloat16 sAhi[128][ASTR];
    __shared__ __align__(16) __nv_bfloat16 sAlo[128][ASTR];
    __shared__ __align__(16) __nv_bfloat16 sBhi[128][ASTR];
    __shared__ __align__(16) __nv_bfloat16 sBlo[128][ASTR];

    int tid = threadIdx.x;
    int wid = tid >> 5, lid = tid & 31;
    int m0  = blockIdx.x * 128;

    int wm = wid & 3;        // M quadrant: rows wm*32 .. +31
    int wn = wid >> 2;       // N half:    cols wn*64 .. +63

    float acc[2][8][4];
    #pragma unroll
    for (int i = 0; i < 2; i++)
        #pragma unroll
        for (int j = 0; j < 8; j++)
            #pragma unroll
            for (int q = 0; q < 4; q++) acc[i][j][q] = 0.f;

    uint32_t aHiBase = smem_u32(&sAhi[0][0]);
    uint32_t aLoBase = smem_u32(&sAlo[0][0]);
    uint32_t bHiBase = smem_u32(&sBhi[0][0]);
    uint32_t bLoBase = smem_u32(&sBlo[0][0]);

    int aRow = lid & 15;
    int aKof = (lid >> 4) * 8;
    int bRow = lid & 7;
    int bKof = ((lid >> 3) & 1) * 8;

    for (int c = 0; c < 8; c++) {
        // ---- stage A chunk (128 rows x 32 k) as bf16 hi/lo
        #pragma unroll
        for (int h = 0; h < 4; h++) {
            int f   = tid + h * 256;      // 0..1023
            int row = f >> 3;
            int kq  = f & 7;
            int m   = m0 + row;
            float4 v = make_float4(0.f, 0.f, 0.f, 0.f);
            if (m < NN) {
                if (c < 4) v = __ldg((const float4*)(x + (size_t)m * 128 + c * 32) + kq);
                else       v = __ldg((const float4*)&g_s4[m][0] + (c - 4) * 8 + kq);
            }
            __nv_bfloat16 h0 = __float2bfloat16(v.x), h1 = __float2bfloat16(v.y);
            __nv_bfloat16 h2 = __float2bfloat16(v.z), h3 = __float2bfloat16(v.w);
            __nv_bfloat16 l0 = __float2bfloat16(v.x - __bfloat162float(h0));
            __nv_bfloat16 l1 = __float2bfloat16(v.y - __bfloat162float(h1));
            __nv_bfloat16 l2 = __float2bfloat16(v.z - __bfloat162float(h2));
            __nv_bfloat16 l3 = __float2bfloat16(v.w - __bfloat162float(h3));
            uint32_t hp0 = (uint32_t)__bfloat16_as_ushort(h0) |
                           ((uint32_t)__bfloat16_as_ushort(h1) << 16);
            uint32_t hp1 = (uint32_t)__bfloat16_as_ushort(h2) |
                           ((uint32_t)__bfloat16_as_ushort(h3) << 16);
            uint32_t lp0 = (uint32_t)__bfloat16_as_ushort(l0) |
                           ((uint32_t)__bfloat16_as_ushort(l1) << 16);
            uint32_t lp1 = (uint32_t)__bfloat16_as_ushort(l2) |
                           ((uint32_t)__bfloat16_as_ushort(l3) << 16);
            *(uint2*)&sAhi[row][kq * 4] = make_uint2(hp0, hp1);
            *(uint2*)&sAlo[row][kq * 4] = make_uint2(lp0, lp1);
        }
        // ---- stage B chunk (128 n x 32 k) from pre-split global
        #pragma unroll
        for (int h = 0; h < 2; h++) {
            int f  = tid + h * 256;
            int n  = f >> 2;
            int kq = f & 3;
            const float4* sh = (const float4*)(g_Bhi + n * 256 + c * 32) + kq;
            const float4* sl = (const float4*)(g_Blo + n * 256 + c * 32) + kq;
            *(float4*)&sBhi[n][kq * 8] = __ldg(sh);
            *(float4*)&sBlo[n][kq * 8] = __ldg(sl);
        }
        __syncthreads();

        #pragma unroll
        for (int ks = 0; ks < 2; ks++) {
            uint32_t ahi[2][4], alo[2][4];
            #pragma unroll
            for (int mt = 0; mt < 2; mt++) {
                uint32_t off = (uint32_t)(((wm * 32 + mt * 16 + aRow) * ASTR
                                           + ks * 16 + aKof) * 2);
                LDSM_X4(ahi[mt][0], ahi[mt][1], ahi[mt][2], ahi[mt][3], aHiBase + off);
                LDSM_X4(alo[mt][0], alo[mt][1], alo[mt][2], alo[mt][3], aLoBase + off);
            }
            #pragma unroll
            for (int nt = 0; nt < 8; nt++) {
                uint32_t bo = (uint32_t)(((wn * 64 + nt * 8 + bRow) * ASTR
                                          + ks * 16 + bKof) * 2);
                uint32_t bhi[2], blo[2];
                LDSM_X2(bhi[0], bhi[1], bHiBase + bo);
                LDSM_X2(blo[0], blo[1], bLoBase + bo);
                #pragma unroll
                for (int mt = 0; mt < 2; mt++) {
                    MMA_BF16(acc[mt][nt], ahi[mt], bhi);
                    MMA_BF16(acc[mt][nt], alo[mt], bhi);
                    MMA_BF16(acc[mt][nt], ahi[mt], blo);
                }
            }
        }
        __syncthreads();
    }

    // ---- epilogue: bias + relu, scale 1/3, RMW out
    const float third = 1.0f / 3.0f;
    int tq = lid >> 2;
    int tr = lid & 3;
    #pragma unroll
    for (int mt = 0; mt < 2; mt++) {
        int rbase = m0 + wm * 32 + mt * 16 + tq;
        #pragma unroll
        for (int hf = 0; hf < 2; hf++) {
            int row = rbase + hf * 8;
            if (row >= NN) continue;
            float* op = out + (size_t)row * 128;
            #pragma unroll
            for (int nt = 0; nt < 8; nt++) {
                int col = wn * 64 + nt * 8 + tr * 2;
                float v0 = acc[mt][nt][hf * 2 + 0] + __ldg(&bias[col]);
                float v1 = acc[mt][nt][hf * 2 + 1] + __ldg(&bias[col + 1]);
                v0 = fmaxf(v0, 0.f) * third;
                v1 = fmaxf(v1, 0.f) * third;
                if (!first) {
                    float2 o = *(const float2*)(op + col);
                    v0 += o.x; v1 += o.y;
                }
                *(float2*)(op + col) = make_float2(v0, v1);
            }
        }
    }
}

// ---------------------------------------------------------------------------
// Launch. Inputs identified BY SIZE (robust to either metadata ordering).
// ---------------------------------------------------------------------------
extern "C" void kernel_launch(void* const* d_in, const int* in_sizes, int n_in,
                              void* d_out, int out_size)
{
    const float* x = nullptr;
    const int*   srcA[3] = {nullptr, nullptr, nullptr};
    const int*   dstA[3] = {nullptr, nullptr, nullptr};
    const float* wA[3]   = {nullptr, nullptr, nullptr};
    const float* WsA[3]  = {nullptr, nullptr, nullptr};
    const float* WnA[3]  = {nullptr, nullptr, nullptr};
    const float* bA[3]   = {nullptr, nullptr, nullptr};

    int nEdge = 0, nMat = 0, nBias = 0;
    for (int i = 0; i < n_in; i++) {
        int sz = in_sizes[i];
        if (sz == NN * DD) {
            x = (const float*)d_in[i];
        } else if (sz == EE) {
            int k = nEdge++;
            int rel = k / 3, kind = k % 3;
            if (rel < 3) {
                if (kind == 0)      srcA[rel] = (const int*)d_in[i];
                else if (kind == 1) dstA[rel] = (const int*)d_in[i];
                else                wA[rel]   = (const float*)d_in[i];
            }
        } else if (sz == DD * HH) {
            int k = nMat++;
            int rel = k / 2;
            if (rel < 3) {
                if ((k & 1) == 0) WsA[rel] = (const float*)d_in[i];
                else              WnA[rel] = (const float*)d_in[i];
            }
        } else if (sz == HH) {
            if (nBias < 3) bA[nBias++] = (const float*)d_in[i];
        }
    }

    float* out = (float*)d_out;

    int edgeBlocks = (EE + 255) / 256;       // 6250
    int nodeBlocks = (NN + 255) / 256;       // 391
    int pullBlocks = (NN * 32 + 255) / 256;  // 12500
    int gemmBlocks = (NN + 127) / 128;       // 782

    for (int r = 0; r < 3; r++) {
        zero_cnt_kernel<<<nodeBlocks, 256>>>();
        hist_kernel<<<edgeBlocks, 256>>>(dstA[r]);
        scan_reduce_kernel<<<SCAN_B, 1024>>>();
        scan_part_kernel<<<1, 128>>>();
        scan_final_kernel<<<SCAN_B, 1024>>>();
        fill_kernel<<<edgeBlocks, 256>>>(srcA[r], dstA[r], wA[r]);
        pull_kernel<<<pullBlocks, 256>>>(x);
        bconv_kernel<<<256, 128>>>(WsA[r], WnA[r]);
        gemm_mma_kernel<<<gemmBlocks, 256>>>(x, bA[r], out, r == 0);
    }
}

// round 10
// speedup vs baseline: 1.8314x; 1.0219x over previous
#include <cuda_runtime.h>
#include <cuda_bf16.h>
#include <cstdint>

#define NN 100000
#define EE 1600000
#define DD 128
#define HH 128

// ---------------------------------------------------------------------------
// Scratch
// ---------------------------------------------------------------------------
__device__ int    g_cnt[NN];                 // in-degree histogram
__device__ int    g_rs[NN + 1];              // CSR row_start
__device__ int    g_cur[NN];                 // fill cursors
__device__ int2   g_pair[EE];                // (src, w-as-int) permuted by dst
__device__ int    g_partraw[128];            // block partial sums
__device__ int    g_part[128];               // scanned partials
// bf16 hi/lo splits: x (once per launch), s (per relation), B^T (per relation)
__device__ __align__(16) __nv_bfloat16 g_xhi[NN * 128];
__device__ __align__(16) __nv_bfloat16 g_xlo[NN * 128];
__device__ __align__(16) __nv_bfloat16 g_shi[NN * 128];
__device__ __align__(16) __nv_bfloat16 g_slo[NN * 128];
__device__ __align__(16) __nv_bfloat16 g_Bhi[128 * 256];   // [n][k]
__device__ __align__(16) __nv_bfloat16 g_Blo[128 * 256];

#define SCAN_B 98          // ceil(NN / 1024)

// ---------------------------------------------------------------------------
// x -> bf16 hi/lo split (once per launch)
// ---------------------------------------------------------------------------
__device__ __forceinline__ void split4(float4 v, uint2& hp, uint2& lp) {
    __nv_bfloat16 h0 = __float2bfloat16(v.x), h1 = __float2bfloat16(v.y);
    __nv_bfloat16 h2 = __float2bfloat16(v.z), h3 = __float2bfloat16(v.w);
    __nv_bfloat16 l0 = __float2bfloat16(v.x - __bfloat162float(h0));
    __nv_bfloat16 l1 = __float2bfloat16(v.y - __bfloat162float(h1));
    __nv_bfloat16 l2 = __float2bfloat16(v.z - __bfloat162float(h2));
    __nv_bfloat16 l3 = __float2bfloat16(v.w - __bfloat162float(h3));
    hp.x = (uint32_t)__bfloat16_as_ushort(h0) | ((uint32_t)__bfloat16_as_ushort(h1) << 16);
    hp.y = (uint32_t)__bfloat16_as_ushort(h2) | ((uint32_t)__bfloat16_as_ushort(h3) << 16);
    lp.x = (uint32_t)__bfloat16_as_ushort(l0) | ((uint32_t)__bfloat16_as_ushort(l1) << 16);
    lp.y = (uint32_t)__bfloat16_as_ushort(l2) | ((uint32_t)__bfloat16_as_ushort(l3) << 16);
}

__global__ void xconv_kernel(const float* __restrict__ x) {
    int i = blockIdx.x * blockDim.x + threadIdx.x;
    if (i >= NN * 32) return;
    float4 v = __ldg((const float4*)x + i);
    uint2 hp, lp;
    split4(v, hp, lp);
    ((uint2*)g_xhi)[i] = hp;
    ((uint2*)g_xlo)[i] = lp;
}

// ---------------------------------------------------------------------------
// CSR build
// ---------------------------------------------------------------------------
__global__ void zero_cnt_kernel() {
    int i = blockIdx.x * blockDim.x + threadIdx.x;
    if (i < NN) g_cnt[i] = 0;
}

__global__ void hist_kernel(const int* __restrict__ dst) {
    int e = blockIdx.x * blockDim.x + threadIdx.x;
    if (e < EE) atomicAdd(&g_cnt[__ldg(&dst[e])], 1);
}

__global__ void scan_reduce_kernel() {
    int b = blockIdx.x, t = threadIdx.x;
    int gi = b * 1024 + t;
    int v = (gi < NN) ? g_cnt[gi] : 0;
    #pragma unroll
    for (int o = 16; o > 0; o >>= 1) v += __shfl_down_sync(0xFFFFFFFFu, v, o);
    __shared__ int wsum[32];
    int lane = t & 31, wid = t >> 5;
    if (lane == 0) wsum[wid] = v;
    __syncthreads();
    if (wid == 0) {
        int s = wsum[lane];
        #pragma unroll
        for (int o = 16; o > 0; o >>= 1) s += __shfl_down_sync(0xFFFFFFFFu, s, o);
        if (lane == 0) g_partraw[b] = s;
    }
}

__global__ void scan_part_kernel() {
    __shared__ int sm[SCAN_B];
    int t = threadIdx.x;
    if (t < SCAN_B) sm[t] = g_partraw[t];
    __syncthreads();
    if (t == 0) {
        int run = 0;
        for (int i = 0; i < SCAN_B; i++) { int c = sm[i]; sm[i] = run; run += c; }
    }
    __syncthreads();
    if (t < SCAN_B) g_part[t] = sm[t];
}

__global__ void scan_final_kernel() {
    int b = blockIdx.x, t = threadIdx.x;
    int gi = b * 1024 + t;
    int lane = t & 31, wid = t >> 5;
    int v = (gi < NN) ? g_cnt[gi] : 0;
    int xv = v;
    #pragma unroll
    for (int o = 1; o < 32; o <<= 1) {
        int y = __shfl_up_sync(0xFFFFFFFFu, xv, o);
        if (lane >= o) xv += y;
    }
    __shared__ int wsum[32];
    if (lane == 31) wsum[wid] = xv;
    __syncthreads();
    if (wid == 0) {
        int s = wsum[lane];
        #pragma unroll
        for (int o = 1; o < 32; o <<= 1) {
            int y = __shfl_up_sync(0xFFFFFFFFu, s, o);
            if (lane >= o) s += y;
        }
        wsum[lane] = s;
    }
    __syncthreads();
    int excl = xv - v + ((wid > 0) ? wsum[wid - 1] : 0) + g_part[b];
    if (gi < NN) { g_rs[gi] = excl; g_cur[gi] = excl; }
    if (gi == NN - 1) g_rs[NN] = excl + v;
}

__global__ void fill_kernel(const int* __restrict__ src, const int* __restrict__ dst,
                            const float* __restrict__ w) {
    int e = blockIdx.x * blockDim.x + threadIdx.x;
    if (e >= EE) return;
    int v = __ldg(&dst[e]);
    int pos = atomicAdd(&g_cur[v], 1);
    g_pair[pos] = make_int2(__ldg(&src[e]), __float_as_int(__ldg(&w[e])));
}

// ---------------------------------------------------------------------------
// Pull: one warp per dst node, unroll-4. Emits pre-normalized bf16 hi/lo.
// ---------------------------------------------------------------------------
__global__ __launch_bounds__(256) void pull_kernel(const float* __restrict__ x) {
    int v = (int)((blockIdx.x * blockDim.x + threadIdx.x) >> 5);
    if (v >= NN) return;
    int lane = threadIdx.x & 31;

    int beg = __ldg(&g_rs[v]);
    int end = __ldg(&g_rs[v + 1]);
    const float4* x4 = (const float4*)x;

    float4 acc = make_float4(0.f, 0.f, 0.f, 0.f);
    int e = beg;
    for (; e + 4 <= end; e += 4) {
        int2 p0 = __ldg(&g_pair[e]);
        int2 p1 = __ldg(&g_pair[e + 1]);
        int2 p2 = __ldg(&g_pair[e + 2]);
        int2 p3 = __ldg(&g_pair[e + 3]);
        float4 a0 = __ldg(x4 + (size_t)p0.x * 32 + lane);
        float4 a1 = __ldg(x4 + (size_t)p1.x * 32 + lane);
        float4 a2 = __ldg(x4 + (size_t)p2.x * 32 + lane);
        float4 a3 = __ldg(x4 + (size_t)p3.x * 32 + lane);
        float w0 = __int_as_float(p0.y), w1 = __int_as_float(p1.y);
        float w2 = __int_as_float(p2.y), w3 = __int_as_float(p3.y);
        acc.x += w0 * a0.x + w1 * a1.x + w2 * a2.x + w3 * a3.x;
        acc.y += w0 * a0.y + w1 * a1.y + w2 * a2.y + w3 * a3.y;
        acc.z += w0 * a0.z + w1 * a1.z + w2 * a2.z + w3 * a3.z;
        acc.w += w0 * a0.w + w1 * a1.w + w2 * a2.w + w3 * a3.w;
    }
    for (; e < end; e++) {
        int2 p = __ldg(&g_pair[e]);
        float4 a = __ldg(x4 + (size_t)p.x * 32 + lane);
        float ww = __int_as_float(p.y);
        acc.x += ww * a.x; acc.y += ww * a.y;
        acc.z += ww * a.z; acc.w += ww * a.w;
    }
    float inv = 1.0f / fmaxf((float)(end - beg), 1.0f);
    acc.x *= inv; acc.y *= inv; acc.z *= inv; acc.w *= inv;
    uint2 hp, lp;
    split4(acc, hp, lp);
    ((uint2*)g_shi)[v * 32 + lane] = hp;
    ((uint2*)g_slo)[v * 32 + lane] = lp;
}

// ---------------------------------------------------------------------------
// B pre-convert: g_Bhi/g_Blo[n][k] = hi/lo(W[k][n]), W = [Ws;Wn]
// ---------------------------------------------------------------------------
__global__ void bconv_kernel(const float* __restrict__ Ws, const float* __restrict__ Wn) {
    int k = blockIdx.x;      // 0..255
    int n = threadIdx.x;     // 0..127
    float wv = (k < 128) ? __ldg(&Ws[k * 128 + n]) : __ldg(&Wn[(k - 128) * 128 + n]);
    __nv_bfloat16 h = __float2bfloat16(wv);
    __nv_bfloat16 l = __float2bfloat16(wv - __bfloat162float(h));
    g_Bhi[n * 256 + k] = h;
    g_Blo[n * 256 + k] = l;
}

// ---------------------------------------------------------------------------
// PTX helpers: ldmatrix + bf16 mma (baseline sm_80+ features)
// ---------------------------------------------------------------------------
__device__ __forceinline__ uint32_t smem_u32(const void* p) {
    uint32_t a;
    asm("{ .reg .u64 t; cvta.to.shared.u64 t, %1; cvt.u32.u64 %0, t; }"
        : "=r"(a) : "l"(p));
    return a;
}
#define LDSM_X4(r0, r1, r2, r3, addr) \
    asm volatile("ldmatrix.sync.aligned.m8n8.x4.shared.b16 {%0,%1,%2,%3}, [%4];" \
        : "=r"(r0), "=r"(r1), "=r"(r2), "=r"(r3) : "r"(addr))
#define MMA_BF16(d, a, b0, b1) \
    asm volatile("mma.sync.aligned.m16n8k16.row.col.f32.bf16.bf16.f32 " \
        "{%0,%1,%2,%3}, {%4,%5,%6,%7}, {%8,%9}, {%0,%1,%2,%3};" \
        : "+f"((d)[0]), "+f"((d)[1]), "+f"((d)[2]), "+f"((d)[3]) \
        : "r"((a)[0]), "r"((a)[1]), "r"((a)[2]), "r"((a)[3]), \
          "r"(b0), "r"(b1))

#define ASTR 40   // smem row stride (b16): conflict-free ldmatrix phases

// ---------------------------------------------------------------------------
// Tensor-core GEMM (mma.sync bf16, 3-pass hi/lo split), one relation:
//   z = [x | s] @ [Ws;Wn] + b ;  out (+)= relu(z)/3
// All operands pre-split bf16 in global -> A staging is a pure copy (no CVT).
// CTA 128x128, 8 warps (4M x 2N). K chunks of 32.
// ---------------------------------------------------------------------------
__global__ __launch_bounds__(256, 2) void gemm_mma_kernel(
    const float* __restrict__ bias, float* __restrict__ out, int first)
{
    __shared__ __align__(16) __nv_bfloat16 sAhi[128][ASTR];
    __shared__ __align__(16) __nv_bfloat16 sAlo[128][ASTR];
    __shared__ __align__(16) __nv_bfloat16 sBhi[128][ASTR];
    __shared__ __align__(16) __nv_bfloat16 sBlo[128][ASTR];

    int tid = threadIdx.x;
    int wid = tid >> 5, lid = tid & 31;
    int m0  = blockIdx.x * 128;

    int wm = wid & 3;        // M quadrant: rows wm*32 .. +31
    int wn = wid >> 2;       // N half:    cols wn*64 .. +63

    float acc[2][8][4];
    #pragma unroll
    for (int i = 0; i < 2; i++)
        #pragma unroll
        for (int j = 0; j < 8; j++)
            #pragma unroll
            for (int q = 0; q < 4; q++) acc[i][j][q] = 0.f;

    uint32_t aHiBase = smem_u32(&sAhi[0][0]);
    uint32_t aLoBase = smem_u32(&sAlo[0][0]);
    uint32_t bHiBase = smem_u32(&sBhi[0][0]);
    uint32_t bLoBase = smem_u32(&sBlo[0][0]);

    int aRow = lid & 15;            // shared by A and B x4 ldmatrix
    int aKof = (lid >> 4) * 8;

    for (int c = 0; c < 8; c++) {
        // ---- stage A chunk (128 rows x 32 k): pure uint4 copy of pre-split bf16
        const uint4* srcHi = (c < 4) ? (const uint4*)g_xhi : (const uint4*)g_shi;
        const uint4* srcLo = (c < 4) ? (const uint4*)g_xlo : (const uint4*)g_slo;
        int cc = c & 3;
        #pragma unroll
        for (int h = 0; h < 2; h++) {
            int f   = tid + h * 256;      // 0..511
            int row = f >> 2;
            int q   = f & 3;              // uint4 (8 bf16) within 32 k
            int m   = m0 + row;
            uint4 vh = make_uint4(0u, 0u, 0u, 0u);
            uint4 vl = make_uint4(0u, 0u, 0u, 0u);
            if (m < NN) {
                size_t idx = (size_t)m * 16 + cc * 4 + q;
                vh = __ldg(srcHi + idx);
                vl = __ldg(srcLo + idx);
            }
            *(uint2*)&sAhi[row][q * 8]     = make_uint2(vh.x, vh.y);
            *(uint2*)&sAhi[row][q * 8 + 4] = make_uint2(vh.z, vh.w);
            *(uint2*)&sAlo[row][q * 8]     = make_uint2(vl.x, vl.y);
            *(uint2*)&sAlo[row][q * 8 + 4] = make_uint2(vl.z, vl.w);
        }
        // ---- stage B chunk (128 n x 32 k) from pre-split global
        #pragma unroll
        for (int h = 0; h < 2; h++) {
            int f  = tid + h * 256;
            int n  = f >> 2;
            int kq = f & 3;
            const uint4* sh = (const uint4*)(g_Bhi + n * 256 + c * 32) + kq;
            const uint4* sl = (const uint4*)(g_Blo + n * 256 + c * 32) + kq;
            uint4 vh = __ldg(sh), vl = __ldg(sl);
            *(uint2*)&sBhi[n][kq * 8]     = make_uint2(vh.x, vh.y);
            *(uint2*)&sBhi[n][kq * 8 + 4] = make_uint2(vh.z, vh.w);
            *(uint2*)&sBlo[n][kq * 8]     = make_uint2(vl.x, vl.y);
            *(uint2*)&sBlo[n][kq * 8 + 4] = make_uint2(vl.z, vl.w);
        }
        __syncthreads();

        #pragma unroll
        for (int ks = 0; ks < 2; ks++) {
            uint32_t ahi[2][4], alo[2][4];
            #pragma unroll
            for (int mt = 0; mt < 2; mt++) {
                uint32_t off = (uint32_t)(((wm * 32 + mt * 16 + aRow) * ASTR
                                           + ks * 16 + aKof) * 2);
                LDSM_X4(ahi[mt][0], ahi[mt][1], ahi[mt][2], ahi[mt][3], aHiBase + off);
                LDSM_X4(alo[mt][0], alo[mt][1], alo[mt][2], alo[mt][3], aLoBase + off);
            }
            // B: one x4 per nt-pair (16 n rows). tiles: {nt,k0},{nt+1,k0},{nt,k8},{nt+1,k8}
            #pragma unroll
            for (int np = 0; np < 4; np++) {
                uint32_t bo = (uint32_t)(((wn * 64 + np * 16 + aRow) * ASTR
                                          + ks * 16 + aKof) * 2);
                uint32_t bh[4], bl[4];
                LDSM_X4(bh[0], bh[1], bh[2], bh[3], bHiBase + bo);
                LDSM_X4(bl[0], bl[1], bl[2], bl[3], bLoBase + bo);
                int nt0 = np * 2, nt1 = np * 2 + 1;
                #pragma unroll
                for (int mt = 0; mt < 2; mt++) {
                    MMA_BF16(acc[mt][nt0], ahi[mt], bh[0], bh[2]);
                    MMA_BF16(acc[mt][nt0], alo[mt], bh[0], bh[2]);
                    MMA_BF16(acc[mt][nt0], ahi[mt], bl[0], bl[2]);
                    MMA_BF16(acc[mt][nt1], ahi[mt], bh[1], bh[3]);
                    MMA_BF16(acc[mt][nt1], alo[mt], bh[1], bh[3]);
                    MMA_BF16(acc[mt][nt1], ahi[mt], bl[1], bl[3]);
                }
            }
        }
        __syncthreads();
    }

    // ---- epilogue: bias + relu, scale 1/3, RMW out
    const float third = 1.0f / 3.0f;
    int tq = lid >> 2;
    int tr = lid & 3;
    #pragma unroll
    for (int mt = 0; mt < 2; mt++) {
        int rbase = m0 + wm * 32 + mt * 16 + tq;
        #pragma unroll
        for (int hf = 0; hf < 2; hf++) {
            int row = rbase + hf * 8;
            if (row >= NN) continue;
            float* op = out + (size_t)row * 128;
            #pragma unroll
            for (int nt = 0; nt < 8; nt++) {
                int col = wn * 64 + nt * 8 + tr * 2;
                float v0 = acc[mt][nt][hf * 2 + 0] + __ldg(&bias[col]);
                float v1 = acc[mt][nt][hf * 2 + 1] + __ldg(&bias[col + 1]);
                v0 = fmaxf(v0, 0.f) * third;
                v1 = fmaxf(v1, 0.f) * third;
                if (!first) {
                    float2 o = *(const float2*)(op + col);
                    v0 += o.x; v1 += o.y;
                }
                *(float2*)(op + col) = make_float2(v0, v1);
            }
        }
    }
}

// ---------------------------------------------------------------------------
// Launch. Inputs identified BY SIZE (robust to either metadata ordering).
// ---------------------------------------------------------------------------
extern "C" void kernel_launch(void* const* d_in, const int* in_sizes, int n_in,
                              void* d_out, int out_size)
{
    const float* x = nullptr;
    const int*   srcA[3] = {nullptr, nullptr, nullptr};
    const int*   dstA[3] = {nullptr, nullptr, nullptr};
    const float* wA[3]   = {nullptr, nullptr, nullptr};
    const float* WsA[3]  = {nullptr, nullptr, nullptr};
    const float* WnA[3]  = {nullptr, nullptr, nullptr};
    const float* bA[3]   = {nullptr, nullptr, nullptr};

    int nEdge = 0, nMat = 0, nBias = 0;
    for (int i = 0; i < n_in; i++) {
        int sz = in_sizes[i];
        if (sz == NN * DD) {
            x = (const float*)d_in[i];
        } else if (sz == EE) {
            int k = nEdge++;
            int rel = k / 3, kind = k % 3;
            if (rel < 3) {
                if (kind == 0)      srcA[rel] = (const int*)d_in[i];
                else if (kind == 1) dstA[rel] = (const int*)d_in[i];
                else                wA[rel]   = (const float*)d_in[i];
            }
        } else if (sz == DD * HH) {
            int k = nMat++;
            int rel = k / 2;
            if (rel < 3) {
                if ((k & 1) == 0) WsA[rel] = (const float*)d_in[i];
                else              WnA[rel] = (const float*)d_in[i];
            }
        } else if (sz == HH) {
            if (nBias < 3) bA[nBias++] = (const float*)d_in[i];
        }
    }

    float* out = (float*)d_out;

    int edgeBlocks = (EE + 255) / 256;       // 6250
    int nodeBlocks = (NN + 255) / 256;       // 391
    int pullBlocks = (NN * 32 + 255) / 256;  // 12500
    int gemmBlocks = (NN + 127) / 128;       // 782
    int xconvBlocks = (NN * 32 + 255) / 256; // 12500

    xconv_kernel<<<xconvBlocks, 256>>>(x);

    for (int r = 0; r < 3; r++) {
        zero_cnt_kernel<<<nodeBlocks, 256>>>();
        hist_kernel<<<edgeBlocks, 256>>>(dstA[r]);
        scan_reduce_kernel<<<SCAN_B, 1024>>>();
        scan_part_kernel<<<1, 128>>>();
        scan_final_kernel<<<SCAN_B, 1024>>>();
        fill_kernel<<<edgeBlocks, 256>>>(srcA[r], dstA[r], wA[r]);
        pull_kernel<<<pullBlocks, 256>>>(x);
        bconv_kernel<<<256, 128>>>(WsA[r], WnA[r]);
        gemm_mma_kernel<<<gemmBlocks, 256>>>(bA[r], out, r == 0);
    }
}

// round 11
// speedup vs baseline: 1.9681x; 1.0746x over previous
#include <cuda_runtime.h>
#include <cuda_bf16.h>
#include <cstdint>

#define NN 100000
#define EE 1600000
#define DD 128
#define HH 128

// ---------------------------------------------------------------------------
// Scratch
// ---------------------------------------------------------------------------
__device__ int    g_cnt[NN];                 // in-degree histogram
__device__ int    g_rs[NN + 1];              // CSR row_start
__device__ int    g_cur[NN];                 // fill cursors
__device__ int2   g_pair[EE];                // (src, w-as-int) permuted by dst
__device__ int    g_partraw[128];            // block partial sums
__device__ int    g_part[128];               // scanned partials
// bf16 hi/lo splits: x (once per launch), s (per relation), B^T (per relation)
__device__ __align__(16) __nv_bfloat16 g_xhi[NN * 128];
__device__ __align__(16) __nv_bfloat16 g_xlo[NN * 128];
__device__ __align__(16) __nv_bfloat16 g_shi[NN * 128];
__device__ __align__(16) __nv_bfloat16 g_slo[NN * 128];
__device__ __align__(16) __nv_bfloat16 g_Bhi[128 * 256];   // [n][k]
__device__ __align__(16) __nv_bfloat16 g_Blo[128 * 256];

#define SCAN_B 98          // ceil(NN / 1024)

// ---------------------------------------------------------------------------
// bf16 hi/lo split helpers
// ---------------------------------------------------------------------------
__device__ __forceinline__ void split4(float4 v, uint2& hp, uint2& lp) {
    __nv_bfloat16 h0 = __float2bfloat16(v.x), h1 = __float2bfloat16(v.y);
    __nv_bfloat16 h2 = __float2bfloat16(v.z), h3 = __float2bfloat16(v.w);
    __nv_bfloat16 l0 = __float2bfloat16(v.x - __bfloat162float(h0));
    __nv_bfloat16 l1 = __float2bfloat16(v.y - __bfloat162float(h1));
    __nv_bfloat16 l2 = __float2bfloat16(v.z - __bfloat162float(h2));
    __nv_bfloat16 l3 = __float2bfloat16(v.w - __bfloat162float(h3));
    hp.x = (uint32_t)__bfloat16_as_ushort(h0) | ((uint32_t)__bfloat16_as_ushort(h1) << 16);
    hp.y = (uint32_t)__bfloat16_as_ushort(h2) | ((uint32_t)__bfloat16_as_ushort(h3) << 16);
    lp.x = (uint32_t)__bfloat16_as_ushort(l0) | ((uint32_t)__bfloat16_as_ushort(l1) << 16);
    lp.y = (uint32_t)__bfloat16_as_ushort(l2) | ((uint32_t)__bfloat16_as_ushort(l3) << 16);
}

__global__ void xconv_kernel(const float* __restrict__ x) {
    int i = blockIdx.x * blockDim.x + threadIdx.x;
    if (i >= NN * 32) return;
    float4 v = __ldg((const float4*)x + i);
    uint2 hp, lp;
    split4(v, hp, lp);
    ((uint2*)g_xhi)[i] = hp;
    ((uint2*)g_xlo)[i] = lp;
}

// ---------------------------------------------------------------------------
// CSR build
// ---------------------------------------------------------------------------
__global__ void zero_cnt_kernel() {
    int i = blockIdx.x * blockDim.x + threadIdx.x;
    if (i < NN) g_cnt[i] = 0;
}

__global__ void hist_kernel(const int* __restrict__ dst) {
    int e = blockIdx.x * blockDim.x + threadIdx.x;
    if (e < EE) atomicAdd(&g_cnt[__ldg(&dst[e])], 1);
}

__global__ void scan_reduce_kernel() {
    int b = blockIdx.x, t = threadIdx.x;
    int gi = b * 1024 + t;
    int v = (gi < NN) ? g_cnt[gi] : 0;
    #pragma unroll
    for (int o = 16; o > 0; o >>= 1) v += __shfl_down_sync(0xFFFFFFFFu, v, o);
    __shared__ int wsum[32];
    int lane = t & 31, wid = t >> 5;
    if (lane == 0) wsum[wid] = v;
    __syncthreads();
    if (wid == 0) {
        int s = wsum[lane];
        #pragma unroll
        for (int o = 16; o > 0; o >>= 1) s += __shfl_down_sync(0xFFFFFFFFu, s, o);
        if (lane == 0) g_partraw[b] = s;
    }
}

__global__ void scan_part_kernel() {
    __shared__ int sm[SCAN_B];
    int t = threadIdx.x;
    if (t < SCAN_B) sm[t] = g_partraw[t];
    __syncthreads();
    if (t == 0) {
        int run = 0;
        for (int i = 0; i < SCAN_B; i++) { int c = sm[i]; sm[i] = run; run += c; }
    }
    __syncthreads();
    if (t < SCAN_B) g_part[t] = sm[t];
}

__global__ void scan_final_kernel() {
    int b = blockIdx.x, t = threadIdx.x;
    int gi = b * 1024 + t;
    int lane = t & 31, wid = t >> 5;
    int v = (gi < NN) ? g_cnt[gi] : 0;
    int xv = v;
    #pragma unroll
    for (int o = 1; o < 32; o <<= 1) {
        int y = __shfl_up_sync(0xFFFFFFFFu, xv, o);
        if (lane >= o) xv += y;
    }
    __shared__ int wsum[32];
    if (lane == 31) wsum[wid] = xv;
    __syncthreads();
    if (wid == 0) {
        int s = wsum[lane];
        #pragma unroll
        for (int o = 1; o < 32; o <<= 1) {
            int y = __shfl_up_sync(0xFFFFFFFFu, s, o);
            if (lane >= o) s += y;
        }
        wsum[lane] = s;
    }
    __syncthreads();
    int excl = xv - v + ((wid > 0) ? wsum[wid - 1] : 0) + g_part[b];
    if (gi < NN) { g_rs[gi] = excl; g_cur[gi] = excl; }
    if (gi == NN - 1) g_rs[NN] = excl + v;
}

__global__ void fill_kernel(const int* __restrict__ src, const int* __restrict__ dst,
                            const float* __restrict__ w) {
    int e = blockIdx.x * blockDim.x + threadIdx.x;
    if (e >= EE) return;
    int v = __ldg(&dst[e]);
    int pos = atomicAdd(&g_cur[v], 1);
    g_pair[pos] = make_int2(__ldg(&src[e]), __float_as_int(__ldg(&w[e])));
}

// ---------------------------------------------------------------------------
// Pull: one warp per dst node, unroll-4. Emits pre-normalized bf16 hi/lo.
// ---------------------------------------------------------------------------
__global__ __launch_bounds__(256) void pull_kernel(const float* __restrict__ x) {
    int v = (int)((blockIdx.x * blockDim.x + threadIdx.x) >> 5);
    if (v >= NN) return;
    int lane = threadIdx.x & 31;

    int beg = __ldg(&g_rs[v]);
    int end = __ldg(&g_rs[v + 1]);
    const float4* x4 = (const float4*)x;

    float4 acc = make_float4(0.f, 0.f, 0.f, 0.f);
    int e = beg;
    for (; e + 4 <= end; e += 4) {
        int2 p0 = __ldg(&g_pair[e]);
        int2 p1 = __ldg(&g_pair[e + 1]);
        int2 p2 = __ldg(&g_pair[e + 2]);
        int2 p3 = __ldg(&g_pair[e + 3]);
        float4 a0 = __ldg(x4 + (size_t)p0.x * 32 + lane);
        float4 a1 = __ldg(x4 + (size_t)p1.x * 32 + lane);
        float4 a2 = __ldg(x4 + (size_t)p2.x * 32 + lane);
        float4 a3 = __ldg(x4 + (size_t)p3.x * 32 + lane);
        float w0 = __int_as_float(p0.y), w1 = __int_as_float(p1.y);
        float w2 = __int_as_float(p2.y), w3 = __int_as_float(p3.y);
        acc.x += w0 * a0.x + w1 * a1.x + w2 * a2.x + w3 * a3.x;
        acc.y += w0 * a0.y + w1 * a1.y + w2 * a2.y + w3 * a3.y;
        acc.z += w0 * a0.z + w1 * a1.z + w2 * a2.z + w3 * a3.z;
        acc.w += w0 * a0.w + w1 * a1.w + w2 * a2.w + w3 * a3.w;
    }
    for (; e < end; e++) {
        int2 p = __ldg(&g_pair[e]);
        float4 a = __ldg(x4 + (size_t)p.x * 32 + lane);
        float ww = __int_as_float(p.y);
        acc.x += ww * a.x; acc.y += ww * a.y;
        acc.z += ww * a.z; acc.w += ww * a.w;
    }
    float inv = 1.0f / fmaxf((float)(end - beg), 1.0f);
    acc.x *= inv; acc.y *= inv; acc.z *= inv; acc.w *= inv;
    uint2 hp, lp;
    split4(acc, hp, lp);
    ((uint2*)g_shi)[v * 32 + lane] = hp;
    ((uint2*)g_slo)[v * 32 + lane] = lp;
}

// ---------------------------------------------------------------------------
// B pre-convert: g_Bhi/g_Blo[n][k] = hi/lo(W[k][n]), W = [Ws;Wn]
// ---------------------------------------------------------------------------
__global__ void bconv_kernel(const float* __restrict__ Ws, const float* __restrict__ Wn) {
    int k = blockIdx.x;      // 0..255
    int n = threadIdx.x;     // 0..127
    float wv = (k < 128) ? __ldg(&Ws[k * 128 + n]) : __ldg(&Wn[(k - 128) * 128 + n]);
    __nv_bfloat16 h = __float2bfloat16(wv);
    __nv_bfloat16 l = __float2bfloat16(wv - __bfloat162float(h));
    g_Bhi[n * 256 + k] = h;
    g_Blo[n * 256 + k] = l;
}

// ---------------------------------------------------------------------------
// PTX helpers
// ---------------------------------------------------------------------------
__device__ __forceinline__ uint32_t smem_u32(const void* p) {
    uint32_t a;
    asm("{ .reg .u64 t; cvta.to.shared.u64 t, %1; cvt.u32.u64 %0, t; }"
        : "=r"(a) : "l"(p));
    return a;
}
#define LDSM_X4(r0, r1, r2, r3, addr) \
    asm volatile("ldmatrix.sync.aligned.m8n8.x4.shared.b16 {%0,%1,%2,%3}, [%4];" \
        : "=r"(r0), "=r"(r1), "=r"(r2), "=r"(r3) : "r"(addr))
#define MMA_BF16(d, a, b0, b1) \
    asm volatile("mma.sync.aligned.m16n8k16.row.col.f32.bf16.bf16.f32 " \
        "{%0,%1,%2,%3}, {%4,%5,%6,%7}, {%8,%9}, {%0,%1,%2,%3};" \
        : "+f"((d)[0]), "+f"((d)[1]), "+f"((d)[2]), "+f"((d)[3]) \
        : "r"((a)[0]), "r"((a)[1]), "r"((a)[2]), "r"((a)[3]), \
          "r"(b0), "r"(b1))
__device__ __forceinline__ void cp_async16(uint32_t saddr, const void* gptr, bool pred) {
    int sz = pred ? 16 : 0;
    asm volatile("cp.async.ca.shared.global [%0], [%1], 16, %2;"
        :: "r"(saddr), "l"(gptr), "r"(sz));
}
#define CP_COMMIT() asm volatile("cp.async.commit_group;" ::: "memory")
#define CP_WAIT1() asm volatile("cp.async.wait_group 1;" ::: "memory")
#define CP_WAIT0() asm volatile("cp.async.wait_group 0;" ::: "memory")

// smem layout (bytes, per stage): Ahi 0, Alo 10240, Bhi 20480, Blo 30720
#define ASTR    40          // b16 row stride (80 B)
#define ROWB    80
#define OFF_ALO 10240
#define OFF_BHI 20480
#define OFF_BLO 30720
#define STAGEB  40960
#define SMEM_DYN (2 * STAGEB)   // 80 KB

// ---------------------------------------------------------------------------
// Tensor-core GEMM with cp.async 2-stage pipeline, one relation:
//   z = [x | s] @ [Ws;Wn] + b ;  out (+)= relu(z)/3
// CTA 128x128, 8 warps (4M x 2N). K chunks of 32, hi/lo 3-pass split.
// ---------------------------------------------------------------------------
__global__ __launch_bounds__(256, 2) void gemm_mma_kernel(
    const float* __restrict__ bias, float* __restrict__ out, int first)
{
    extern __shared__ __align__(16) char dynsmem[];
    uint32_t sbase = smem_u32(dynsmem);

    int tid = threadIdx.x;
    int wid = tid >> 5, lid = tid & 31;
    int m0  = blockIdx.x * 128;

    int wm = wid & 3;        // M quadrant
    int wn = wid >> 2;       // N half

    float acc[2][8][4];
    #pragma unroll
    for (int i = 0; i < 2; i++)
        #pragma unroll
        for (int j = 0; j < 8; j++)
            #pragma unroll
            for (int q = 0; q < 4; q++) acc[i][j][q] = 0.f;

    // staging indices (constant over chunks)
    int f0 = tid, f1 = tid + 256;
    int row0 = f0 >> 2, q0 = f0 & 3;
    int row1 = f1 >> 2, q1 = f1 & 3;
    bool p0 = (m0 + row0) < NN, p1 = (m0 + row1) < NN;
    size_t aIdx0 = (size_t)(p0 ? (m0 + row0) : 0) * 16 + q0;   // + cc*4 later
    size_t aIdx1 = (size_t)(p1 ? (m0 + row1) : 0) * 16 + q1;
    size_t bIdx0 = (size_t)row0 * 32 + q0;                      // + c*4 later
    size_t bIdx1 = (size_t)row1 * 32 + q1;
    uint32_t sA0 = (uint32_t)(row0 * ROWB + q0 * 16);
    uint32_t sA1 = (uint32_t)(row1 * ROWB + q1 * 16);

    auto stage = [&](int c) {
        uint32_t base = sbase + (uint32_t)(c & 1) * STAGEB;
        const uint4* srcHi = (c < 4) ? (const uint4*)g_xhi : (const uint4*)g_shi;
        const uint4* srcLo = (c < 4) ? (const uint4*)g_xlo : (const uint4*)g_slo;
        int cc4 = (c & 3) * 4;
        cp_async16(base + sA0,           srcHi + aIdx0 + cc4, p0);
        cp_async16(base + sA1,           srcHi + aIdx1 + cc4, p1);
        cp_async16(base + OFF_ALO + sA0, srcLo + aIdx0 + cc4, p0);
        cp_async16(base + OFF_ALO + sA1, srcLo + aIdx1 + cc4, p1);
        cp_async16(base + OFF_BHI + sA0, (const uint4*)g_Bhi + bIdx0 + c * 4, true);
        cp_async16(base + OFF_BHI + sA1, (const uint4*)g_Bhi + bIdx1 + c * 4, true);
        cp_async16(base + OFF_BLO + sA0, (const uint4*)g_Blo + bIdx0 + c * 4, true);
        cp_async16(base + OFF_BLO + sA1, (const uint4*)g_Blo + bIdx1 + c * 4, true);
    };

    int aRow = lid & 15;
    int aKof = (lid >> 4) * 8;

    stage(0);
    CP_COMMIT();

    for (int c = 0; c < 8; c++) {
        if (c < 7) { stage(c + 1); CP_COMMIT(); CP_WAIT1(); }
        else       { CP_WAIT0(); }
        __syncthreads();

        uint32_t base = sbase + (uint32_t)(c & 1) * STAGEB;
        uint32_t aHiBase = base, aLoBase = base + OFF_ALO;
        uint32_t bHiBase = base + OFF_BHI, bLoBase = base + OFF_BLO;

        #pragma unroll
        for (int ks = 0; ks < 2; ks++) {
            uint32_t ahi[2][4], alo[2][4];
            #pragma unroll
            for (int mt = 0; mt < 2; mt++) {
                uint32_t off = (uint32_t)(((wm * 32 + mt * 16 + aRow) * ASTR
                                           + ks * 16 + aKof) * 2);
                LDSM_X4(ahi[mt][0], ahi[mt][1], ahi[mt][2], ahi[mt][3], aHiBase + off);
                LDSM_X4(alo[mt][0], alo[mt][1], alo[mt][2], alo[mt][3], aLoBase + off);
            }
            #pragma unroll
            for (int np = 0; np < 4; np++) {
                uint32_t bo = (uint32_t)(((wn * 64 + np * 16 + aRow) * ASTR
                                          + ks * 16 + aKof) * 2);
                uint32_t bh[4], bl[4];
                LDSM_X4(bh[0], bh[1], bh[2], bh[3], bHiBase + bo);
                LDSM_X4(bl[0], bl[1], bl[2], bl[3], bLoBase + bo);
                int nt0 = np * 2, nt1 = np * 2 + 1;
                #pragma unroll
                for (int mt = 0; mt < 2; mt++) {
                    MMA_BF16(acc[mt][nt0], ahi[mt], bh[0], bh[2]);
                    MMA_BF16(acc[mt][nt0], alo[mt], bh[0], bh[2]);
                    MMA_BF16(acc[mt][nt0], ahi[mt], bl[0], bl[2]);
                    MMA_BF16(acc[mt][nt1], ahi[mt], bh[1], bh[3]);
                    MMA_BF16(acc[mt][nt1], alo[mt], bh[1], bh[3]);
                    MMA_BF16(acc[mt][nt1], ahi[mt], bl[1], bl[3]);
                }
            }
        }
        __syncthreads();
    }

    // ---- epilogue: bias + relu, scale 1/3, RMW out
    const float third = 1.0f / 3.0f;
    int tq = lid >> 2;
    int tr = lid & 3;
    #pragma unroll
    for (int mt = 0; mt < 2; mt++) {
        int rbase = m0 + wm * 32 + mt * 16 + tq;
        #pragma unroll
        for (int hf = 0; hf < 2; hf++) {
            int row = rbase + hf * 8;
            if (row >= NN) continue;
            float* op = out + (size_t)row * 128;
            #pragma unroll
            for (int nt = 0; nt < 8; nt++) {
                int col = wn * 64 + nt * 8 + tr * 2;
                float v0 = acc[mt][nt][hf * 2 + 0] + __ldg(&bias[col]);
                float v1 = acc[mt][nt][hf * 2 + 1] + __ldg(&bias[col + 1]);
                v0 = fmaxf(v0, 0.f) * third;
                v1 = fmaxf(v1, 0.f) * third;
                if (!first) {
                    float2 o = *(const float2*)(op + col);
                    v0 += o.x; v1 += o.y;
                }
                *(float2*)(op + col) = make_float2(v0, v1);
            }
        }
    }
}

// ---------------------------------------------------------------------------
// Launch. Inputs identified BY SIZE (robust to either metadata ordering).
// ---------------------------------------------------------------------------
extern "C" void kernel_launch(void* const* d_in, const int* in_sizes, int n_in,
                              void* d_out, int out_size)
{
    const float* x = nullptr;
    const int*   srcA[3] = {nullptr, nullptr, nullptr};
    const int*   dstA[3] = {nullptr, nullptr, nullptr};
    const float* wA[3]   = {nullptr, nullptr, nullptr};
    const float* WsA[3]  = {nullptr, nullptr, nullptr};
    const float* WnA[3]  = {nullptr, nullptr, nullptr};
    const float* bA[3]   = {nullptr, nullptr, nullptr};

    int nEdge = 0, nMat = 0, nBias = 0;
    for (int i = 0; i < n_in; i++) {
        int sz = in_sizes[i];
        if (sz == NN * DD) {
            x = (const float*)d_in[i];
        } else if (sz == EE) {
            int k = nEdge++;
            int rel = k / 3, kind = k % 3;
            if (rel < 3) {
                if (kind == 0)      srcA[rel] = (const int*)d_in[i];
                else if (kind == 1) dstA[rel] = (const int*)d_in[i];
                else                wA[rel]   = (const float*)d_in[i];
            }
        } else if (sz == DD * HH) {
            int k = nMat++;
            int rel = k / 2;
            if (rel < 3) {
                if ((k & 1) == 0) WsA[rel] = (const float*)d_in[i];
                else              WnA[rel] = (const float*)d_in[i];
            }
        } else if (sz == HH) {
            if (nBias < 3) bA[nBias++] = (const float*)d_in[i];
        }
    }

    float* out = (float*)d_out;

    cudaFuncSetAttribute(gemm_mma_kernel,
                         cudaFuncAttributeMaxDynamicSharedMemorySize, SMEM_DYN);

    int edgeBlocks = (EE + 255) / 256;       // 6250
    int nodeBlocks = (NN + 255) / 256;       // 391
    int pullBlocks = (NN * 32 + 255) / 256;  // 12500
    int gemmBlocks = (NN + 127) / 128;       // 782
    int xconvBlocks = (NN * 32 + 255) / 256; // 12500

    xconv_kernel<<<xconvBlocks, 256>>>(x);

    for (int r = 0; r < 3; r++) {
        zero_cnt_kernel<<<nodeBlocks, 256>>>();
        hist_kernel<<<edgeBlocks, 256>>>(dstA[r]);
        scan_reduce_kernel<<<SCAN_B, 1024>>>();
        scan_part_kernel<<<1, 128>>>();
        scan_final_kernel<<<SCAN_B, 1024>>>();
        fill_kernel<<<edgeBlocks, 256>>>(srcA[r], dstA[r], wA[r]);
        pull_kernel<<<pullBlocks, 256>>>(x);
        bconv_kernel<<<256, 128>>>(WsA[r], WnA[r]);
        gemm_mma_kernel<<<gemmBlocks, 256, SMEM_DYN>>>(bA[r], out, r == 0);
    }
}

// round 13
// speedup vs baseline: 2.0194x; 1.0261x over previous
#include <cuda_runtime.h>
#include <cuda_bf16.h>
#include <cstdint>

#define NN 100000
#define EE 1600000
#define DD 128
#define HH 128

// ---------------------------------------------------------------------------
// Scratch (per-relation where needed)
// ---------------------------------------------------------------------------
__device__ int    g_cnt[3][NN];
__device__ int    g_rs[3][NN + 1];
__device__ int    g_cur[3][NN];
__device__ int2   g_pair[3][EE];
__device__ int    g_partraw[3][128];
__device__ int    g_part[3][128];
__device__ __align__(16) __nv_bfloat16 g_xhi[NN * 128];
__device__ __align__(16) __nv_bfloat16 g_xlo[NN * 128];
__device__ __align__(16) __nv_bfloat16 g_shi[3][NN * 128];
__device__ __align__(16) __nv_bfloat16 g_slo[3][NN * 128];
__device__ __align__(16) __nv_bfloat16 g_Bhi[3][128 * 256];   // [n][k]
__device__ __align__(16) __nv_bfloat16 g_Blo[3][128 * 256];

#define SCAN_B 98          // ceil(NN / 1024)

// ---------------------------------------------------------------------------
// bf16 hi/lo split helper
// ---------------------------------------------------------------------------
__device__ __forceinline__ void split4(float4 v, uint2& hp, uint2& lp) {
    __nv_bfloat16 h0 = __float2bfloat16(v.x), h1 = __float2bfloat16(v.y);
    __nv_bfloat16 h2 = __float2bfloat16(v.z), h3 = __float2bfloat16(v.w);
    __nv_bfloat16 l0 = __float2bfloat16(v.x - __bfloat162float(h0));
    __nv_bfloat16 l1 = __float2bfloat16(v.y - __bfloat162float(h1));
    __nv_bfloat16 l2 = __float2bfloat16(v.z - __bfloat162float(h2));
    __nv_bfloat16 l3 = __float2bfloat16(v.w - __bfloat162float(h3));
    hp.x = (uint32_t)__bfloat16_as_ushort(h0) | ((uint32_t)__bfloat16_as_ushort(h1) << 16);
    hp.y = (uint32_t)__bfloat16_as_ushort(h2) | ((uint32_t)__bfloat16_as_ushort(h3) << 16);
    lp.x = (uint32_t)__bfloat16_as_ushort(l0) | ((uint32_t)__bfloat16_as_ushort(l1) << 16);
    lp.y = (uint32_t)__bfloat16_as_ushort(l2) | ((uint32_t)__bfloat16_as_ushort(l3) << 16);
}

__global__ void xconv_kernel(const float* __restrict__ x) {
    int i = blockIdx.x * blockDim.x + threadIdx.x;
    if (i >= NN * 32) return;
    float4 v = __ldg((const float4*)x + i);
    uint2 hp, lp;
    split4(v, hp, lp);
    ((uint2*)g_xhi)[i] = hp;
    ((uint2*)g_xlo)[i] = lp;
}

// ---------------------------------------------------------------------------
// Batched CSR build (blockIdx.y = relation)
// ---------------------------------------------------------------------------
__global__ void zero_cnt_kernel() {
    int i = blockIdx.x * blockDim.x + threadIdx.x;
    if (i < NN) g_cnt[blockIdx.y][i] = 0;
}

__global__ void hist_kernel(const int* __restrict__ d0, const int* __restrict__ d1,
                            const int* __restrict__ d2) {
    int r = blockIdx.y;
    const int* dst = (r == 0) ? d0 : ((r == 1) ? d1 : d2);
    int e = blockIdx.x * blockDim.x + threadIdx.x;
    if (e < EE) atomicAdd(&g_cnt[r][__ldg(&dst[e])], 1);
}

__global__ void scan_reduce_kernel() {
    int r = blockIdx.y;
    int b = blockIdx.x, t = threadIdx.x;
    int gi = b * 1024 + t;
    int v = (gi < NN) ? g_cnt[r][gi] : 0;
    #pragma unroll
    for (int o = 16; o > 0; o >>= 1) v += __shfl_down_sync(0xFFFFFFFFu, v, o);
    __shared__ int wsum[32];
    int lane = t & 31, wid = t >> 5;
    if (lane == 0) wsum[wid] = v;
    __syncthreads();
    if (wid == 0) {
        int s = wsum[lane];
        #pragma unroll
        for (int o = 16; o > 0; o >>= 1) s += __shfl_down_sync(0xFFFFFFFFu, s, o);
        if (lane == 0) g_partraw[r][b] = s;
    }
}

__global__ void scan_part_kernel() {
    int r = blockIdx.y;
    __shared__ int sm[SCAN_B];
    int t = threadIdx.x;
    if (t < SCAN_B) sm[t] = g_partraw[r][t];
    __syncthreads();
    if (t == 0) {
        int run = 0;
        for (int i = 0; i < SCAN_B; i++) { int c = sm[i]; sm[i] = run; run += c; }
    }
    __syncthreads();
    if (t < SCAN_B) g_part[r][t] = sm[t];
}

__global__ void scan_final_kernel() {
    int r = blockIdx.y;
    int b = blockIdx.x, t = threadIdx.x;
    int gi = b * 1024 + t;
    int lane = t & 31, wid = t >> 5;
    int v = (gi < NN) ? g_cnt[r][gi] : 0;
    int xv = v;
    #pragma unroll
    for (int o = 1; o < 32; o <<= 1) {
        int y = __shfl_up_sync(0xFFFFFFFFu, xv, o);
        if (lane >= o) xv += y;
    }
    __shared__ int wsum[32];
    if (lane == 31) wsum[wid] = xv;
    __syncthreads();
    if (wid == 0) {
        int s = wsum[lane];
        #pragma unroll
        for (int o = 1; o < 32; o <<= 1) {
            int y = __shfl_up_sync(0xFFFFFFFFu, s, o);
            if (lane >= o) s += y;
        }
        wsum[lane] = s;
    }
    __syncthreads();
    int excl = xv - v + ((wid > 0) ? wsum[wid - 1] : 0) + g_part[r][b];
    if (gi < NN) { g_rs[r][gi] = excl; g_cur[r][gi] = excl; }
    if (gi == NN - 1) g_rs[r][NN] = excl + v;
}

__global__ void fill_kernel(
    const int* __restrict__ s0, const int* __restrict__ d0, const float* __restrict__ w0,
    const int* __restrict__ s1, const int* __restrict__ d1, const float* __restrict__ w1,
    const int* __restrict__ s2, const int* __restrict__ d2, const float* __restrict__ w2)
{
    int r = blockIdx.y;
    const int* src = (r == 0) ? s0 : ((r == 1) ? s1 : s2);
    const int* dst = (r == 0) ? d0 : ((r == 1) ? d1 : d2);
    const float* w = (r == 0) ? w0 : ((r == 1) ? w1 : w2);
    int e = blockIdx.x * blockDim.x + threadIdx.x;
    if (e >= EE) return;
    int v = __ldg(&dst[e]);
    int pos = atomicAdd(&g_cur[r][v], 1);
    g_pair[r][pos] = make_int2(__ldg(&src[e]), __float_as_int(__ldg(&w[e])));
}

// ---------------------------------------------------------------------------
// Batched pull: one warp per (node, relation). Emits pre-normalized bf16 hi/lo.
// ---------------------------------------------------------------------------
__global__ __launch_bounds__(256) void pull_kernel(const float* __restrict__ x) {
    int r = blockIdx.y;
    int v = (int)((blockIdx.x * blockDim.x + threadIdx.x) >> 5);
    if (v >= NN) return;
    int lane = threadIdx.x & 31;

    int beg = __ldg(&g_rs[r][v]);
    int end = __ldg(&g_rs[r][v + 1]);
    const float4* x4 = (const float4*)x;
    const int2* pair = g_pair[r];

    float4 acc = make_float4(0.f, 0.f, 0.f, 0.f);
    int e = beg;
    for (; e + 4 <= end; e += 4) {
        int2 p0 = __ldg(&pair[e]);
        int2 p1 = __ldg(&pair[e + 1]);
        int2 p2 = __ldg(&pair[e + 2]);
        int2 p3 = __ldg(&pair[e + 3]);
        float4 a0 = __ldg(x4 + (size_t)p0.x * 32 + lane);
        float4 a1 = __ldg(x4 + (size_t)p1.x * 32 + lane);
        float4 a2 = __ldg(x4 + (size_t)p2.x * 32 + lane);
        float4 a3 = __ldg(x4 + (size_t)p3.x * 32 + lane);
        float w0 = __int_as_float(p0.y), w1 = __int_as_float(p1.y);
        float w2 = __int_as_float(p2.y), w3 = __int_as_float(p3.y);
        acc.x += w0 * a0.x + w1 * a1.x + w2 * a2.x + w3 * a3.x;
        acc.y += w0 * a0.y + w1 * a1.y + w2 * a2.y + w3 * a3.y;
        acc.z += w0 * a0.z + w1 * a1.z + w2 * a2.z + w3 * a3.z;
        acc.w += w0 * a0.w + w1 * a1.w + w2 * a2.w + w3 * a3.w;
    }
    for (; e < end; e++) {
        int2 p = __ldg(&pair[e]);
        float4 a = __ldg(x4 + (size_t)p.x * 32 + lane);
        float ww = __int_as_float(p.y);
        acc.x += ww * a.x; acc.y += ww * a.y;
        acc.z += ww * a.z; acc.w += ww * a.w;
    }
    float inv = 1.0f / fmaxf((float)(end - beg), 1.0f);
    acc.x *= inv; acc.y *= inv; acc.z *= inv; acc.w *= inv;
    uint2 hp, lp;
    split4(acc, hp, lp);
    ((uint2*)g_shi[r])[v * 32 + lane] = hp;
    ((uint2*)g_slo[r])[v * 32 + lane] = lp;
}

// ---------------------------------------------------------------------------
// Batched B pre-convert
// ---------------------------------------------------------------------------
__global__ void bconv_kernel(
    const float* __restrict__ Ws0, const float* __restrict__ Wn0,
    const float* __restrict__ Ws1, const float* __restrict__ Wn1,
    const float* __restrict__ Ws2, const float* __restrict__ Wn2)
{
    int r = blockIdx.y;
    const float* Ws = (r == 0) ? Ws0 : ((r == 1) ? Ws1 : Ws2);
    const float* Wn = (r == 0) ? Wn0 : ((r == 1) ? Wn1 : Wn2);
    int k = blockIdx.x;      // 0..255
    int n = threadIdx.x;     // 0..127
    float wv = (k < 128) ? __ldg(&Ws[k * 128 + n]) : __ldg(&Wn[(k - 128) * 128 + n]);
    __nv_bfloat16 h = __float2bfloat16(wv);
    __nv_bfloat16 l = __float2bfloat16(wv - __bfloat162float(h));
    g_Bhi[r][n * 256 + k] = h;
    g_Blo[r][n * 256 + k] = l;
}

__global__ void zero_out_kernel(float* __restrict__ out) {
    int i = blockIdx.x * blockDim.x + threadIdx.x;
    if (i < NN * 32) ((float4*)out)[i] = make_float4(0.f, 0.f, 0.f, 0.f);
}

// ---------------------------------------------------------------------------
// PTX helpers
// ---------------------------------------------------------------------------
__device__ __forceinline__ uint32_t smem_u32(const void* p) {
    uint32_t a;
    asm("{ .reg .u64 t; cvta.to.shared.u64 t, %1; cvt.u32.u64 %0, t; }"
        : "=r"(a) : "l"(p));
    return a;
}
#define LDSM_X4(r0, r1, r2, r3, addr) \
    asm volatile("ldmatrix.sync.aligned.m8n8.x4.shared.b16 {%0,%1,%2,%3}, [%4];" \
        : "=r"(r0), "=r"(r1), "=r"(r2), "=r"(r3) : "r"(addr))
#define MMA_BF16(d, a, b0, b1) \
    asm volatile("mma.sync.aligned.m16n8k16.row.col.f32.bf16.bf16.f32 " \
        "{%0,%1,%2,%3}, {%4,%5,%6,%7}, {%8,%9}, {%0,%1,%2,%3};" \
        : "+f"((d)[0]), "+f"((d)[1]), "+f"((d)[2]), "+f"((d)[3]) \
        : "r"((a)[0]), "r"((a)[1]), "r"((a)[2]), "r"((a)[3]), \
          "r"(b0), "r"(b1))
__device__ __forceinline__ void cp_async16(uint32_t saddr, const void* gptr, bool pred) {
    int sz = pred ? 16 : 0;
    asm volatile("cp.async.ca.shared.global [%0], [%1], 16, %2;"
        :: "r"(saddr), "l"(gptr), "r"(sz));
}
#define CP_COMMIT() asm volatile("cp.async.commit_group;" ::: "memory")
#define CP_WAIT1() asm volatile("cp.async.wait_group 1;" ::: "memory")
#define CP_WAIT0() asm volatile("cp.async.wait_group 0;" ::: "memory")

// smem layout (bytes, per stage): Ahi 0, Alo 10240, Bhi 20480, Blo 30720
#define ASTR    40          // b16 row stride (80 B)
#define ROWB    80
#define OFF_ALO 10240
#define OFF_BHI 20480
#define OFF_BLO 30720
#define STAGEB  40960
#define SMEM_DYN (2 * STAGEB)   // 80 KB
#define EPI_STRIDE 68           // fp32 epilogue staging row stride (272 B)

// ---------------------------------------------------------------------------
// Fused tensor-core GEMM, grid (782, 3): blockIdx.y = relation.
//   z_r = [x | s_r] @ [Ws_r;Wn_r] + b_r ;  out += relu(z_r)/3  (atomic f32x4)
// CTA 128x128, 8 warps (4M x 2N). K chunks of 32, hi/lo 3-pass split.
// ---------------------------------------------------------------------------
__global__ __launch_bounds__(256, 2) void gemm_mma_kernel(
    const float* __restrict__ b0, const float* __restrict__ b1,
    const float* __restrict__ b2, float* __restrict__ out)
{
    extern __shared__ __align__(16) char dynsmem[];
    uint32_t sbase = smem_u32(dynsmem);

    int r   = blockIdx.y;
    int tid = threadIdx.x;
    int wid = tid >> 5, lid = tid & 31;
    int m0  = blockIdx.x * 128;

    int wm = wid & 3;        // M quadrant
    int wn = wid >> 2;       // N half

    const __nv_bfloat16* sHi = g_shi[r];
    const __nv_bfloat16* sLo = g_slo[r];
    const __nv_bfloat16* BHi = g_Bhi[r];
    const __nv_bfloat16* BLo = g_Blo[r];
    const float* bias = (r == 0) ? b0 : ((r == 1) ? b1 : b2);

    float acc[2][8][4];
    #pragma unroll
    for (int i = 0; i < 2; i++)
        #pragma unroll
        for (int j = 0; j < 8; j++)
            #pragma unroll
            for (int q = 0; q < 4; q++) acc[i][j][q] = 0.f;

    // staging indices (constant over chunks)
    int f0 = tid, f1 = tid + 256;
    int row0 = f0 >> 2, q0 = f0 & 3;
    int row1 = f1 >> 2, q1 = f1 & 3;
    bool p0 = (m0 + row0) < NN, p1 = (m0 + row1) < NN;
    size_t aIdx0 = (size_t)(p0 ? (m0 + row0) : 0) * 16 + q0;
    size_t aIdx1 = (size_t)(p1 ? (m0 + row1) : 0) * 16 + q1;
    size_t bIdx0 = (size_t)row0 * 32 + q0;
    size_t bIdx1 = (size_t)row1 * 32 + q1;
    uint32_t sA0 = (uint32_t)(row0 * ROWB + q0 * 16);
    uint32_t sA1 = (uint32_t)(row1 * ROWB + q1 * 16);

    auto stage = [&](int c) {
        uint32_t base = sbase + (uint32_t)(c & 1) * STAGEB;
        const uint4* srcHi = (c < 4) ? (const uint4*)g_xhi : (const uint4*)sHi;
        const uint4* srcLo = (c < 4) ? (const uint4*)g_xlo : (const uint4*)sLo;
        int cc4 = (c & 3) * 4;
        cp_async16(base + sA0,           srcHi + aIdx0 + cc4, p0);
        cp_async16(base + sA1,           srcHi + aIdx1 + cc4, p1);
        cp_async16(base + OFF_ALO + sA0, srcLo + aIdx0 + cc4, p0);
        cp_async16(base + OFF_ALO + sA1, srcLo + aIdx1 + cc4, p1);
        cp_async16(base + OFF_BHI + sA0, (const uint4*)BHi + bIdx0 + c * 4, true);
        cp_async16(base + OFF_BHI + sA1, (const uint4*)BHi + bIdx1 + c * 4, true);
        cp_async16(base + OFF_BLO + sA0, (const uint4*)BLo + bIdx0 + c * 4, true);
        cp_async16(base + OFF_BLO + sA1, (const uint4*)BLo + bIdx1 + c * 4, true);
    };

    int aRow = lid & 15;
    int aKof = (lid >> 4) * 8;

    stage(0);
    CP_COMMIT();

    for (int c = 0; c < 8; c++) {
        if (c < 7) { stage(c + 1); CP_COMMIT(); CP_WAIT1(); }
        else       { CP_WAIT0(); }
        __syncthreads();

        uint32_t base = sbase + (uint32_t)(c & 1) * STAGEB;
        uint32_t aHiBase = base, aLoBase = base + OFF_ALO;
        uint32_t bHiBase = base + OFF_BHI, bLoBase = base + OFF_BLO;

        #pragma unroll
        for (int ks = 0; ks < 2; ks++) {
            uint32_t ahi[2][4], alo[2][4];
            #pragma unroll
            for (int mt = 0; mt < 2; mt++) {
                uint32_t off = (uint32_t)(((wm * 32 + mt * 16 + aRow) * ASTR
                                           + ks * 16 + aKof) * 2);
                LDSM_X4(ahi[mt][0], ahi[mt][1], ahi[mt][2], ahi[mt][3], aHiBase + off);
                LDSM_X4(alo[mt][0], alo[mt][1], alo[mt][2], alo[mt][3], aLoBase + off);
            }
            #pragma unroll
            for (int np = 0; np < 4; np++) {
                uint32_t bo = (uint32_t)(((wn * 64 + np * 16 + aRow) * ASTR
                                          + ks * 16 + aKof) * 2);
                uint32_t bh[4], bl[4];
                LDSM_X4(bh[0], bh[1], bh[2], bh[3], bHiBase + bo);
                LDSM_X4(bl[0], bl[1], bl[2], bl[3], bLoBase + bo);
                int nt0 = np * 2, nt1 = np * 2 + 1;
                #pragma unroll
                for (int mt = 0; mt < 2; mt++) {
                    MMA_BF16(acc[mt][nt0], ahi[mt], bh[0], bh[2]);
                    MMA_BF16(acc[mt][nt0], alo[mt], bh[0], bh[2]);
                    MMA_BF16(acc[mt][nt0], ahi[mt], bl[0], bl[2]);
                    MMA_BF16(acc[mt][nt1], ahi[mt], bh[1], bh[3]);
                    MMA_BF16(acc[mt][nt1], alo[mt], bh[1], bh[3]);
                    MMA_BF16(acc[mt][nt1], ahi[mt], bl[1], bl[3]);
                }
            }
        }
        __syncthreads();
    }

    // ---- epilogue: bias+relu+1/3 -> warp-private smem tile -> float4 atomicAdd
    const float third = 1.0f / 3.0f;
    int tq = lid >> 2;
    int tr = lid & 3;
    float* wsm = (float*)(dynsmem + wid * (32 * EPI_STRIDE * 4));

    #pragma unroll
    for (int mt = 0; mt < 2; mt++) {
        #pragma unroll
        for (int hf = 0; hf < 2; hf++) {
            int row = mt * 16 + hf * 8 + tq;       // 0..31 (local)
            #pragma unroll
            for (int nt = 0; nt < 8; nt++) {
                int col = nt * 8 + tr * 2;         // 0..63 (local)
                float v0 = acc[mt][nt][hf * 2 + 0] + __ldg(&bias[wn * 64 + col]);
                float v1 = acc[mt][nt][hf * 2 + 1] + __ldg(&bias[wn * 64 + col + 1]);
                v0 = fmaxf(v0, 0.f) * third;
                v1 = fmaxf(v1, 0.f) * third;
                *(float2*)(wsm + row * EPI_STRIDE + col) = make_float2(v0, v1);
            }
        }
    }
    __syncwarp();

    // 32 rows x 16 float4 = 512 float4 per warp -> 16 iterations of 32 lanes
    float4* out4 = (float4*)out;
    #pragma unroll
    for (int i = 0; i < 16; i++) {
        int idx = i * 32 + lid;        // 0..511
        int row = idx >> 4;            // 0..31
        int c4  = idx & 15;            // 0..15
        int rg = m0 + wm * 32 + row;
        if (rg < NN) {
            float4 v = *(const float4*)(wsm + row * EPI_STRIDE + c4 * 4);
            atomicAdd(&out4[(size_t)rg * 32 + wn * 16 + c4], v);
        }
    }
}

// ---------------------------------------------------------------------------
// Launch. Inputs identified BY SIZE (robust to either metadata ordering).
// ---------------------------------------------------------------------------
extern "C" void kernel_launch(void* const* d_in, const int* in_sizes, int n_in,
                              void* d_out, int out_size)
{
    const float* x = nullptr;
    const int*   srcA[3] = {nullptr, nullptr, nullptr};
    const int*   dstA[3] = {nullptr, nullptr, nullptr};
    const float* wA[3]   = {nullptr, nullptr, nullptr};
    const float* WsA[3]  = {nullptr, nullptr, nullptr};
    const float* WnA[3]  = {nullptr, nullptr, nullptr};
    const float* bA[3]   = {nullptr, nullptr, nullptr};

    int nEdge = 0, nMat = 0, nBias = 0;
    for (int i = 0; i < n_in; i++) {
        int sz = in_sizes[i];
        if (sz == NN * DD) {
            x = (const float*)d_in[i];
        } else if (sz == EE) {
            int k = nEdge++;
            int rel = k / 3, kind = k % 3;
            if (rel < 3) {
                if (kind == 0)      srcA[rel] = (const int*)d_in[i];
                else if (kind == 1) dstA[rel] = (const int*)d_in[i];
                else                wA[rel]   = (const float*)d_in[i];
            }
        } else if (sz == DD * HH) {
            int k = nMat++;
            int rel = k / 2;
            if (rel < 3) {
                if ((k & 1) == 0) WsA[rel] = (const float*)d_in[i];
                else              WnA[rel] = (const float*)d_in[i];
            }
        } else if (sz == HH) {
            if (nBias < 3) bA[nBias++] = (const float*)d_in[i];
        }
    }

    float* out = (float*)d_out;

    cudaFuncSetAttribute(gemm_mma_kernel,
                         cudaFuncAttributeMaxDynamicSharedMemorySize, SMEM_DYN);

    dim3 edgeG((EE + 255) / 256, 3);
    dim3 nodeG((NN + 255) / 256, 3);
    dim3 pullG((NN * 32 + 255) / 256, 3);
    dim3 scanRG(SCAN_B, 3);
    dim3 scanPG(1, 3);
    dim3 bconvG(256, 3);
    dim3 gemmG((NN + 127) / 128, 3);
    int xconvBlocks = (NN * 32 + 255) / 256;

    xconv_kernel<<<xconvBlocks, 256>>>(x);
    zero_cnt_kernel<<<nodeG, 256>>>();
    hist_kernel<<<edgeG, 256>>>(dstA[0], dstA[1], dstA[2]);
    scan_reduce_kernel<<<scanRG, 1024>>>();
    scan_part_kernel<<<scanPG, 128>>>();
    scan_final_kernel<<<scanRG, 1024>>>();
    fill_kernel<<<edgeG, 256>>>(srcA[0], dstA[0], wA[0],
                                srcA[1], dstA[1], wA[1],
                                srcA[2], dstA[2], wA[2]);
    pull_kernel<<<pullG, 256>>>(x);
    bconv_kernel<<<bconvG, 128>>>(WsA[0], WnA[0], WsA[1], WnA[1], WsA[2], WnA[2]);
    zero_out_kernel<<<xconvBlocks, 256>>>(out);
    gemm_mma_kernel<<<gemmG, 256, SMEM_DYN>>>(bA[0], bA[1], bA[2], out);
}

// round 14
// speedup vs baseline: 2.2711x; 1.1247x over previous
#include <cuda_runtime.h>
#include <cuda_fp16.h>
#include <cstdint>

#define NN 100000
#define EE 1600000
#define DD 128
#define HH 128

// ---------------------------------------------------------------------------
// Scratch (per-relation where needed)
// ---------------------------------------------------------------------------
__device__ int    g_cnt[3][NN];
__device__ int    g_rs[3][NN + 1];
__device__ int    g_cur[3][NN];
__device__ int2   g_pair[3][EE];
__device__ int    g_partraw[3][128];
__device__ int    g_part[3][128];
// fp16 hi/lo splits for A operands; B kept hi-only (2-pass scheme)
__device__ __align__(16) __half g_xhi[NN * 128];
__device__ __align__(16) __half g_xlo[NN * 128];
__device__ __align__(16) __half g_shi[3][NN * 128];
__device__ __align__(16) __half g_slo[3][NN * 128];
__device__ __align__(16) __half g_Bhi[3][128 * 256];   // [n][k]

#define SCAN_B 98          // ceil(NN / 1024)

// ---------------------------------------------------------------------------
// fp16 hi/lo split helper
// ---------------------------------------------------------------------------
__device__ __forceinline__ void split4h(float4 v, uint2& hp, uint2& lp) {
    __half h0 = __float2half_rn(v.x), h1 = __float2half_rn(v.y);
    __half h2 = __float2half_rn(v.z), h3 = __float2half_rn(v.w);
    __half l0 = __float2half_rn(v.x - __half2float(h0));
    __half l1 = __float2half_rn(v.y - __half2float(h1));
    __half l2 = __float2half_rn(v.z - __half2float(h2));
    __half l3 = __float2half_rn(v.w - __half2float(h3));
    hp.x = (uint32_t)__half_as_ushort(h0) | ((uint32_t)__half_as_ushort(h1) << 16);
    hp.y = (uint32_t)__half_as_ushort(h2) | ((uint32_t)__half_as_ushort(h3) << 16);
    lp.x = (uint32_t)__half_as_ushort(l0) | ((uint32_t)__half_as_ushort(l1) << 16);
    lp.y = (uint32_t)__half_as_ushort(l2) | ((uint32_t)__half_as_ushort(l3) << 16);
}

// x -> fp16 hi/lo split; also zero-initializes out (same element count).
__global__ void xconv_kernel(const float* __restrict__ x, float* __restrict__ out) {
    int i = blockIdx.x * blockDim.x + threadIdx.x;
    if (i >= NN * 32) return;
    float4 v = __ldg((const float4*)x + i);
    uint2 hp, lp;
    split4h(v, hp, lp);
    ((uint2*)g_xhi)[i] = hp;
    ((uint2*)g_xlo)[i] = lp;
    ((float4*)out)[i] = make_float4(0.f, 0.f, 0.f, 0.f);
}

// ---------------------------------------------------------------------------
// Batched CSR build (blockIdx.y = relation)
// ---------------------------------------------------------------------------
__global__ void zero_cnt_kernel() {
    int i = blockIdx.x * blockDim.x + threadIdx.x;
    if (i < NN) g_cnt[blockIdx.y][i] = 0;
}

__global__ void hist_kernel(const int* __restrict__ d0, const int* __restrict__ d1,
                            const int* __restrict__ d2) {
    int r = blockIdx.y;
    const int* dst = (r == 0) ? d0 : ((r == 1) ? d1 : d2);
    int e = blockIdx.x * blockDim.x + threadIdx.x;
    if (e < EE) atomicAdd(&g_cnt[r][__ldg(&dst[e])], 1);
}

__global__ void scan_reduce_kernel() {
    int r = blockIdx.y;
    int b = blockIdx.x, t = threadIdx.x;
    int gi = b * 1024 + t;
    int v = (gi < NN) ? g_cnt[r][gi] : 0;
    #pragma unroll
    for (int o = 16; o > 0; o >>= 1) v += __shfl_down_sync(0xFFFFFFFFu, v, o);
    __shared__ int wsum[32];
    int lane = t & 31, wid = t >> 5;
    if (lane == 0) wsum[wid] = v;
    __syncthreads();
    if (wid == 0) {
        int s = wsum[lane];
        #pragma unroll
        for (int o = 16; o > 0; o >>= 1) s += __shfl_down_sync(0xFFFFFFFFu, s, o);
        if (lane == 0) g_partraw[r][b] = s;
    }
}

__global__ void scan_part_kernel() {
    int r = blockIdx.y;
    __shared__ int sm[SCAN_B];
    int t = threadIdx.x;
    if (t < SCAN_B) sm[t] = g_partraw[r][t];
    __syncthreads();
    if (t == 0) {
        int run = 0;
        for (int i = 0; i < SCAN_B; i++) { int c = sm[i]; sm[i] = run; run += c; }
    }
    __syncthreads();
    if (t < SCAN_B) g_part[r][t] = sm[t];
}

__global__ void scan_final_kernel() {
    int r = blockIdx.y;
    int b = blockIdx.x, t = threadIdx.x;
    int gi = b * 1024 + t;
    int lane = t & 31, wid = t >> 5;
    int v = (gi < NN) ? g_cnt[r][gi] : 0;
    int xv = v;
    #pragma unroll
    for (int o = 1; o < 32; o <<= 1) {
        int y = __shfl_up_sync(0xFFFFFFFFu, xv, o);
        if (lane >= o) xv += y;
    }
    __shared__ int wsum[32];
    if (lane == 31) wsum[wid] = xv;
    __syncthreads();
    if (wid == 0) {
        int s = wsum[lane];
        #pragma unroll
        for (int o = 1; o < 32; o <<= 1) {
            int y = __shfl_up_sync(0xFFFFFFFFu, s, o);
            if (lane >= o) s += y;
        }
        wsum[lane] = s;
    }
    __syncthreads();
    int excl = xv - v + ((wid > 0) ? wsum[wid - 1] : 0) + g_part[r][b];
    if (gi < NN) { g_rs[r][gi] = excl; g_cur[r][gi] = excl; }
    if (gi == NN - 1) g_rs[r][NN] = excl + v;
}

__global__ void fill_kernel(
    const int* __restrict__ s0, const int* __restrict__ d0, const float* __restrict__ w0,
    const int* __restrict__ s1, const int* __restrict__ d1, const float* __restrict__ w1,
    const int* __restrict__ s2, const int* __restrict__ d2, const float* __restrict__ w2)
{
    int r = blockIdx.y;
    const int* src = (r == 0) ? s0 : ((r == 1) ? s1 : s2);
    const int* dst = (r == 0) ? d0 : ((r == 1) ? d1 : d2);
    const float* w = (r == 0) ? w0 : ((r == 1) ? w1 : w2);
    int e = blockIdx.x * blockDim.x + threadIdx.x;
    if (e >= EE) return;
    int v = __ldg(&dst[e]);
    int pos = atomicAdd(&g_cur[r][v], 1);
    g_pair[r][pos] = make_int2(__ldg(&src[e]), __float_as_int(__ldg(&w[e])));
}

// ---------------------------------------------------------------------------
// Batched pull: one warp per (node, relation). Emits pre-normalized fp16 hi/lo.
// ---------------------------------------------------------------------------
__global__ __launch_bounds__(256) void pull_kernel(const float* __restrict__ x) {
    int r = blockIdx.y;
    int v = (int)((blockIdx.x * blockDim.x + threadIdx.x) >> 5);
    if (v >= NN) return;
    int lane = threadIdx.x & 31;

    int beg = __ldg(&g_rs[r][v]);
    int end = __ldg(&g_rs[r][v + 1]);
    const float4* x4 = (const float4*)x;
    const int2* pair = g_pair[r];

    float4 acc = make_float4(0.f, 0.f, 0.f, 0.f);
    int e = beg;
    for (; e + 4 <= end; e += 4) {
        int2 p0 = __ldg(&pair[e]);
        int2 p1 = __ldg(&pair[e + 1]);
        int2 p2 = __ldg(&pair[e + 2]);
        int2 p3 = __ldg(&pair[e + 3]);
        float4 a0 = __ldg(x4 + (size_t)p0.x * 32 + lane);
        float4 a1 = __ldg(x4 + (size_t)p1.x * 32 + lane);
        float4 a2 = __ldg(x4 + (size_t)p2.x * 32 + lane);
        float4 a3 = __ldg(x4 + (size_t)p3.x * 32 + lane);
        float w0 = __int_as_float(p0.y), w1 = __int_as_float(p1.y);
        float w2 = __int_as_float(p2.y), w3 = __int_as_float(p3.y);
        acc.x += w0 * a0.x + w1 * a1.x + w2 * a2.x + w3 * a3.x;
        acc.y += w0 * a0.y + w1 * a1.y + w2 * a2.y + w3 * a3.y;
        acc.z += w0 * a0.z + w1 * a1.z + w2 * a2.z + w3 * a3.z;
        acc.w += w0 * a0.w + w1 * a1.w + w2 * a2.w + w3 * a3.w;
    }
    for (; e < end; e++) {
        int2 p = __ldg(&pair[e]);
        float4 a = __ldg(x4 + (size_t)p.x * 32 + lane);
        float ww = __int_as_float(p.y);
        acc.x += ww * a.x; acc.y += ww * a.y;
        acc.z += ww * a.z; acc.w += ww * a.w;
    }
    float inv = 1.0f / fmaxf((float)(end - beg), 1.0f);
    acc.x *= inv; acc.y *= inv; acc.z *= inv; acc.w *= inv;
    uint2 hp, lp;
    split4h(acc, hp, lp);
    ((uint2*)g_shi[r])[v * 32 + lane] = hp;
    ((uint2*)g_slo[r])[v * 32 + lane] = lp;
}

// ---------------------------------------------------------------------------
// Batched B pre-convert (fp16 hi only): g_Bhi[r][n][k] = fp16(W[k][n])
// ---------------------------------------------------------------------------
__global__ void bconv_kernel(
    const float* __restrict__ Ws0, const float* __restrict__ Wn0,
    const float* __restrict__ Ws1, const float* __restrict__ Wn1,
    const float* __restrict__ Ws2, const float* __restrict__ Wn2)
{
    int r = blockIdx.y;
    const float* Ws = (r == 0) ? Ws0 : ((r == 1) ? Ws1 : Ws2);
    const float* Wn = (r == 0) ? Wn0 : ((r == 1) ? Wn1 : Wn2);
    int k = blockIdx.x;      // 0..255
    int n = threadIdx.x;     // 0..127
    float wv = (k < 128) ? __ldg(&Ws[k * 128 + n]) : __ldg(&Wn[(k - 128) * 128 + n]);
    g_Bhi[r][n * 256 + k] = __float2half_rn(wv);
}

// ---------------------------------------------------------------------------
// PTX helpers
// ---------------------------------------------------------------------------
__device__ __forceinline__ uint32_t smem_u32(const void* p) {
    uint32_t a;
    asm("{ .reg .u64 t; cvta.to.shared.u64 t, %1; cvt.u32.u64 %0, t; }"
        : "=r"(a) : "l"(p));
    return a;
}
#define LDSM_X4(r0, r1, r2, r3, addr) \
    asm volatile("ldmatrix.sync.aligned.m8n8.x4.shared.b16 {%0,%1,%2,%3}, [%4];" \
        : "=r"(r0), "=r"(r1), "=r"(r2), "=r"(r3) : "r"(addr))
#define MMA_F16(d, a, b0, b1) \
    asm volatile("mma.sync.aligned.m16n8k16.row.col.f32.f16.f16.f32 " \
        "{%0,%1,%2,%3}, {%4,%5,%6,%7}, {%8,%9}, {%0,%1,%2,%3};" \
        : "+f"((d)[0]), "+f"((d)[1]), "+f"((d)[2]), "+f"((d)[3]) \
        : "r"((a)[0]), "r"((a)[1]), "r"((a)[2]), "r"((a)[3]), \
          "r"(b0), "r"(b1))
__device__ __forceinline__ void cp_async16(uint32_t saddr, const void* gptr, bool pred) {
    int sz = pred ? 16 : 0;
    asm volatile("cp.async.ca.shared.global [%0], [%1], 16, %2;"
        :: "r"(saddr), "l"(gptr), "r"(sz));
}
#define CP_COMMIT() asm volatile("cp.async.commit_group;" ::: "memory")
#define CP_WAIT1() asm volatile("cp.async.wait_group 1;" ::: "memory")
#define CP_WAIT0() asm volatile("cp.async.wait_group 0;" ::: "memory")

// smem layout (bytes, per stage): Ahi 0, Alo 10240, Bhi 20480
#define ASTR    40          // b16 row stride (80 B)
#define ROWB    80
#define OFF_ALO 10240
#define OFF_BHI 20480
#define STAGEB  30720
#define EPI_STRIDE 68           // fp32 epilogue staging row stride
#define SMEM_DYN 69632          // max(2*STAGEB=61440, 8*32*EPI_STRIDE*4=69632)

// ---------------------------------------------------------------------------
// Fused tensor-core GEMM, grid (782, 3): blockIdx.y = relation.
//   z_r = [x | s_r] @ fp16(W_r) + b_r ;  out += relu(z_r)/3  (atomic f32x4)
// fp16 2-pass: (Ahi + Alo) x Bhi, fp32 accum. CTA 128x128, 8 warps.
// ---------------------------------------------------------------------------
__global__ __launch_bounds__(256, 2) void gemm_mma_kernel(
    const float* __restrict__ b0, const float* __restrict__ b1,
    const float* __restrict__ b2, float* __restrict__ out)
{
    extern __shared__ __align__(16) char dynsmem[];
    uint32_t sbase = smem_u32(dynsmem);

    int r   = blockIdx.y;
    int tid = threadIdx.x;
    int wid = tid >> 5, lid = tid & 31;
    int m0  = blockIdx.x * 128;

    int wm = wid & 3;        // M quadrant
    int wn = wid >> 2;       // N half

    const __half* sHi = g_shi[r];
    const __half* sLo = g_slo[r];
    const __half* BHi = g_Bhi[r];
    const float* bias = (r == 0) ? b0 : ((r == 1) ? b1 : b2);

    float acc[2][8][4];
    #pragma unroll
    for (int i = 0; i < 2; i++)
        #pragma unroll
        for (int j = 0; j < 8; j++)
            #pragma unroll
            for (int q = 0; q < 4; q++) acc[i][j][q] = 0.f;

    // staging indices (constant over chunks)
    int f0 = tid, f1 = tid + 256;
    int row0 = f0 >> 2, q0 = f0 & 3;
    int row1 = f1 >> 2, q1 = f1 & 3;
    bool p0 = (m0 + row0) < NN, p1 = (m0 + row1) < NN;
    size_t aIdx0 = (size_t)(p0 ? (m0 + row0) : 0) * 16 + q0;
    size_t aIdx1 = (size_t)(p1 ? (m0 + row1) : 0) * 16 + q1;
    size_t bIdx0 = (size_t)row0 * 32 + q0;
    size_t bIdx1 = (size_t)row1 * 32 + q1;
    uint32_t sA0 = (uint32_t)(row0 * ROWB + q0 * 16);
    uint32_t sA1 = (uint32_t)(row1 * ROWB + q1 * 16);

    auto stage = [&](int c) {
        uint32_t base = sbase + (uint32_t)(c & 1) * STAGEB;
        const uint4* srcHi = (c < 4) ? (const uint4*)g_xhi : (const uint4*)sHi;
        const uint4* srcLo = (c < 4) ? (const uint4*)g_xlo : (const uint4*)sLo;
        int cc4 = (c & 3) * 4;
        cp_async16(base + sA0,           srcHi + aIdx0 + cc4, p0);
        cp_async16(base + sA1,           srcHi + aIdx1 + cc4, p1);
        cp_async16(base + OFF_ALO + sA0, srcLo + aIdx0 + cc4, p0);
        cp_async16(base + OFF_ALO + sA1, srcLo + aIdx1 + cc4, p1);
        cp_async16(base + OFF_BHI + sA0, (const uint4*)BHi + bIdx0 + c * 4, true);
        cp_async16(base + OFF_BHI + sA1, (const uint4*)BHi + bIdx1 + c * 4, true);
    };

    int aRow = lid & 15;
    int aKof = (lid >> 4) * 8;

    stage(0);
    CP_COMMIT();

    for (int c = 0; c < 8; c++) {
        if (c < 7) { stage(c + 1); CP_COMMIT(); CP_WAIT1(); }
        else       { CP_WAIT0(); }
        __syncthreads();

        uint32_t base = sbase + (uint32_t)(c & 1) * STAGEB;
        uint32_t aHiBase = base, aLoBase = base + OFF_ALO;
        uint32_t bHiBase = base + OFF_BHI;

        #pragma unroll
        for (int ks = 0; ks < 2; ks++) {
            uint32_t ahi[2][4], alo[2][4];
            #pragma unroll
            for (int mt = 0; mt < 2; mt++) {
                uint32_t off = (uint32_t)(((wm * 32 + mt * 16 + aRow) * ASTR
                                           + ks * 16 + aKof) * 2);
                LDSM_X4(ahi[mt][0], ahi[mt][1], ahi[mt][2], ahi[mt][3], aHiBase + off);
                LDSM_X4(alo[mt][0], alo[mt][1], alo[mt][2], alo[mt][3], aLoBase + off);
            }
            #pragma unroll
            for (int np = 0; np < 4; np++) {
                uint32_t bo = (uint32_t)(((wn * 64 + np * 16 + aRow) * ASTR
                                          + ks * 16 + aKof) * 2);
                uint32_t bh[4];
                LDSM_X4(bh[0], bh[1], bh[2], bh[3], bHiBase + bo);
                int nt0 = np * 2, nt1 = np * 2 + 1;
                #pragma unroll
                for (int mt = 0; mt < 2; mt++) {
                    MMA_F16(acc[mt][nt0], ahi[mt], bh[0], bh[2]);
                    MMA_F16(acc[mt][nt0], alo[mt], bh[0], bh[2]);
                    MMA_F16(acc[mt][nt1], ahi[mt], bh[1], bh[3]);
                    MMA_F16(acc[mt][nt1], alo[mt], bh[1], bh[3]);
                }
            }
        }
        __syncthreads();
    }

    // ---- epilogue: bias+relu+1/3 -> warp-private smem tile -> float4 atomicAdd
    const float third = 1.0f / 3.0f;
    int tq = lid >> 2;
    int tr = lid & 3;
    float* wsm = (float*)(dynsmem + wid * (32 * EPI_STRIDE * 4));

    #pragma unroll
    for (int mt = 0; mt < 2; mt++) {
        #pragma unroll
        for (int hf = 0; hf < 2; hf++) {
            int row = mt * 16 + hf * 8 + tq;       // 0..31 (local)
            #pragma unroll
            for (int nt = 0; nt < 8; nt++) {
                int col = nt * 8 + tr * 2;         // 0..63 (local)
                float v0 = acc[mt][nt][hf * 2 + 0] + __ldg(&bias[wn * 64 + col]);
                float v1 = acc[mt][nt][hf * 2 + 1] + __ldg(&bias[wn * 64 + col + 1]);
                v0 = fmaxf(v0, 0.f) * third;
                v1 = fmaxf(v1, 0.f) * third;
                *(float2*)(wsm + row * EPI_STRIDE + col) = make_float2(v0, v1);
            }
        }
    }
    __syncwarp();

    // 32 rows x 16 float4 = 512 float4 per warp -> 16 iterations of 32 lanes
    float4* out4 = (float4*)out;
    #pragma unroll
    for (int i = 0; i < 16; i++) {
        int idx = i * 32 + lid;        // 0..511
        int row = idx >> 4;            // 0..31
        int c4  = idx & 15;            // 0..15
        int rg = m0 + wm * 32 + row;
        if (rg < NN) {
            float4 v = *(const float4*)(wsm + row * EPI_STRIDE + c4 * 4);
            atomicAdd(&out4[(size_t)rg * 32 + wn * 16 + c4], v);
        }
    }
}

// ---------------------------------------------------------------------------
// Launch. Inputs identified BY SIZE (robust to either metadata ordering).
// ---------------------------------------------------------------------------
extern "C" void kernel_launch(void* const* d_in, const int* in_sizes, int n_in,
                              void* d_out, int out_size)
{
    const float* x = nullptr;
    const int*   srcA[3] = {nullptr, nullptr, nullptr};
    const int*   dstA[3] = {nullptr, nullptr, nullptr};
    const float* wA[3]   = {nullptr, nullptr, nullptr};
    const float* WsA[3]  = {nullptr, nullptr, nullptr};
    const float* WnA[3]  = {nullptr, nullptr, nullptr};
    const float* bA[3]   = {nullptr, nullptr, nullptr};

    int nEdge = 0, nMat = 0, nBias = 0;
    for (int i = 0; i < n_in; i++) {
        int sz = in_sizes[i];
        if (sz == NN * DD) {
            x = (const float*)d_in[i];
        } else if (sz == EE) {
            int k = nEdge++;
            int rel = k / 3, kind = k % 3;
            if (rel < 3) {
                if (kind == 0)      srcA[rel] = (const int*)d_in[i];
                else if (kind == 1) dstA[rel] = (const int*)d_in[i];
                else                wA[rel]   = (const float*)d_in[i];
            }
        } else if (sz == DD * HH) {
            int k = nMat++;
            int rel = k / 2;
            if (rel < 3) {
                if ((k & 1) == 0) WsA[rel] = (const float*)d_in[i];
                else              WnA[rel] = (const float*)d_in[i];
            }
        } else if (sz == HH) {
            if (nBias < 3) bA[nBias++] = (const float*)d_in[i];
        }
    }

    float* out = (float*)d_out;

    cudaFuncSetAttribute(gemm_mma_kernel,
                         cudaFuncAttributeMaxDynamicSharedMemorySize, SMEM_DYN);

    dim3 edgeG((EE + 255) / 256, 3);
    dim3 nodeG((NN + 255) / 256, 3);
    dim3 pullG((NN * 32 + 255) / 256, 3);
    dim3 scanRG(SCAN_B, 3);
    dim3 scanPG(1, 3);
    dim3 bconvG(256, 3);
    dim3 gemmG((NN + 127) / 128, 3);
    int xconvBlocks = (NN * 32 + 255) / 256;

    xconv_kernel<<<xconvBlocks, 256>>>(x, out);
    zero_cnt_kernel<<<nodeG, 256>>>();
    hist_kernel<<<edgeG, 256>>>(dstA[0], dstA[1], dstA[2]);
    scan_reduce_kernel<<<scanRG, 1024>>>();
    scan_part_kernel<<<scanPG, 128>>>();
    scan_final_kernel<<<scanRG, 1024>>>();
    fill_kernel<<<edgeG, 256>>>(srcA[0], dstA[0], wA[0],
                                srcA[1], dstA[1], wA[1],
                                srcA[2], dstA[2], wA[2]);
    pull_kernel<<<pullG, 256>>>(x);
    bconv_kernel<<<bconvG, 128>>>(WsA[0], WnA[0], WsA[1], WnA[1], WsA[2], WnA[2]);
    gemm_mma_kernel<<<gemmG, 256, SMEM_DYN>>>(bA[0], bA[1], bA[2], out);
}

// round 15
// speedup vs baseline: 2.6998x; 1.1887x over previous
#include <cuda_runtime.h>
#include <cuda_fp16.h>
#include <cstdint>

#define NN 100000
#define EE 1600000
#define DD 128
#define HH 128

// ---------------------------------------------------------------------------
// Scratch (per-relation where needed)
// ---------------------------------------------------------------------------
__device__ int    g_cnt[3][NN];
__device__ int    g_rs[3][NN + 1];
__device__ int    g_cur[3][NN];
__device__ int2   g_pair[3][EE];
__device__ int    g_partraw[3][128];
__device__ int    g_part[3][128];
// fp16 hi/lo splits for A operands; B kept hi-only (2-pass scheme)
__device__ __align__(16) __half g_xhi[NN * 128];
__device__ __align__(16) __half g_xlo[NN * 128];
__device__ __align__(16) __half g_shi[3][NN * 128];
__device__ __align__(16) __half g_slo[3][NN * 128];
__device__ __align__(16) __half g_Bhi[3][128 * 256];   // [n][k]

#define SCAN_B 98          // ceil(NN / 1024)

// ---------------------------------------------------------------------------
// fp16 hi/lo split helper
// ---------------------------------------------------------------------------
__device__ __forceinline__ void split4h(float4 v, uint2& hp, uint2& lp) {
    __half h0 = __float2half_rn(v.x), h1 = __float2half_rn(v.y);
    __half h2 = __float2half_rn(v.z), h3 = __float2half_rn(v.w);
    __half l0 = __float2half_rn(v.x - __half2float(h0));
    __half l1 = __float2half_rn(v.y - __half2float(h1));
    __half l2 = __float2half_rn(v.z - __half2float(h2));
    __half l3 = __float2half_rn(v.w - __half2float(h3));
    hp.x = (uint32_t)__half_as_ushort(h0) | ((uint32_t)__half_as_ushort(h1) << 16);
    hp.y = (uint32_t)__half_as_ushort(h2) | ((uint32_t)__half_as_ushort(h3) << 16);
    lp.x = (uint32_t)__half_as_ushort(l0) | ((uint32_t)__half_as_ushort(l1) << 16);
    lp.y = (uint32_t)__half_as_ushort(l2) | ((uint32_t)__half_as_ushort(l3) << 16);
}

// x -> fp16 hi/lo split; also zero-initializes out (same element count).
__global__ void xconv_kernel(const float* __restrict__ x, float* __restrict__ out) {
    int i = blockIdx.x * blockDim.x + threadIdx.x;
    if (i >= NN * 32) return;
    float4 v = __ldg((const float4*)x + i);
    uint2 hp, lp;
    split4h(v, hp, lp);
    ((uint2*)g_xhi)[i] = hp;
    ((uint2*)g_xlo)[i] = lp;
    ((float4*)out)[i] = make_float4(0.f, 0.f, 0.f, 0.f);
}

// ---------------------------------------------------------------------------
// Batched CSR build (blockIdx.y = relation)
// ---------------------------------------------------------------------------
__global__ void zero_cnt_kernel() {
    int i = blockIdx.x * blockDim.x + threadIdx.x;
    if (i < NN) g_cnt[blockIdx.y][i] = 0;
}

__global__ void hist_kernel(const int* __restrict__ d0, const int* __restrict__ d1,
                            const int* __restrict__ d2) {
    int r = blockIdx.y;
    const int* dst = (r == 0) ? d0 : ((r == 1) ? d1 : d2);
    int e = blockIdx.x * blockDim.x + threadIdx.x;
    if (e < EE) atomicAdd(&g_cnt[r][__ldg(&dst[e])], 1);
}

__global__ void scan_reduce_kernel() {
    int r = blockIdx.y;
    int b = blockIdx.x, t = threadIdx.x;
    int gi = b * 1024 + t;
    int v = (gi < NN) ? g_cnt[r][gi] : 0;
    #pragma unroll
    for (int o = 16; o > 0; o >>= 1) v += __shfl_down_sync(0xFFFFFFFFu, v, o);
    __shared__ int wsum[32];
    int lane = t & 31, wid = t >> 5;
    if (lane == 0) wsum[wid] = v;
    __syncthreads();
    if (wid == 0) {
        int s = wsum[lane];
        #pragma unroll
        for (int o = 16; o > 0; o >>= 1) s += __shfl_down_sync(0xFFFFFFFFu, s, o);
        if (lane == 0) g_partraw[r][b] = s;
    }
}

__global__ void scan_part_kernel() {
    int r = blockIdx.y;
    __shared__ int sm[SCAN_B];
    int t = threadIdx.x;
    if (t < SCAN_B) sm[t] = g_partraw[r][t];
    __syncthreads();
    if (t == 0) {
        int run = 0;
        for (int i = 0; i < SCAN_B; i++) { int c = sm[i]; sm[i] = run; run += c; }
    }
    __syncthreads();
    if (t < SCAN_B) g_part[r][t] = sm[t];
}

__global__ void scan_final_kernel() {
    int r = blockIdx.y;
    int b = blockIdx.x, t = threadIdx.x;
    int gi = b * 1024 + t;
    int lane = t & 31, wid = t >> 5;
    int v = (gi < NN) ? g_cnt[r][gi] : 0;
    int xv = v;
    #pragma unroll
    for (int o = 1; o < 32; o <<= 1) {
        int y = __shfl_up_sync(0xFFFFFFFFu, xv, o);
        if (lane >= o) xv += y;
    }
    __shared__ int wsum[32];
    if (lane == 31) wsum[wid] = xv;
    __syncthreads();
    if (wid == 0) {
        int s = wsum[lane];
        #pragma unroll
        for (int o = 1; o < 32; o <<= 1) {
            int y = __shfl_up_sync(0xFFFFFFFFu, s, o);
            if (lane >= o) s += y;
        }
        wsum[lane] = s;
    }
    __syncthreads();
    int excl = xv - v + ((wid > 0) ? wsum[wid - 1] : 0) + g_part[r][b];
    if (gi < NN) { g_rs[r][gi] = excl; g_cur[r][gi] = excl; }
    if (gi == NN - 1) g_rs[r][NN] = excl + v;
}

__global__ void fill_kernel(
    const int* __restrict__ s0, const int* __restrict__ d0, const float* __restrict__ w0,
    const int* __restrict__ s1, const int* __restrict__ d1, const float* __restrict__ w1,
    const int* __restrict__ s2, const int* __restrict__ d2, const float* __restrict__ w2)
{
    int r = blockIdx.y;
    const int* src = (r == 0) ? s0 : ((r == 1) ? s1 : s2);
    const int* dst = (r == 0) ? d0 : ((r == 1) ? d1 : d2);
    const float* w = (r == 0) ? w0 : ((r == 1) ? w1 : w2);
    int e = blockIdx.x * blockDim.x + threadIdx.x;
    if (e >= EE) return;
    int v = __ldg(&dst[e]);
    int pos = atomicAdd(&g_cur[r][v], 1);
    g_pair[r][pos] = make_int2(__ldg(&src[e]), __float_as_int(__ldg(&w[e])));
}

// ---------------------------------------------------------------------------
// Batched pull: one warp per (node, relation). Gathers from the fp16 copy of x
// (g_xhi, 256 B/row -> half the L2 traffic of fp32), accumulates fp32, emits
// pre-normalized fp16 hi/lo.
// ---------------------------------------------------------------------------
__global__ __launch_bounds__(256) void pull_kernel() {
    int r = blockIdx.y;
    int v = (int)((blockIdx.x * blockDim.x + threadIdx.x) >> 5);
    if (v >= NN) return;
    int lane = threadIdx.x & 31;

    int beg = __ldg(&g_rs[r][v]);
    int end = __ldg(&g_rs[r][v + 1]);
    const uint2* xh = (const uint2*)g_xhi;   // row = 32 uint2 (4 halves each)
    const int2* pair = g_pair[r];

    float4 acc = make_float4(0.f, 0.f, 0.f, 0.f);
    int e = beg;
    for (; e + 4 <= end; e += 4) {
        int2 p0 = __ldg(&pair[e]);
        int2 p1 = __ldg(&pair[e + 1]);
        int2 p2 = __ldg(&pair[e + 2]);
        int2 p3 = __ldg(&pair[e + 3]);
        uint2 r0 = __ldg(xh + (size_t)p0.x * 32 + lane);
        uint2 r1 = __ldg(xh + (size_t)p1.x * 32 + lane);
        uint2 r2 = __ldg(xh + (size_t)p2.x * 32 + lane);
        uint2 r3 = __ldg(xh + (size_t)p3.x * 32 + lane);
        float w0 = __int_as_float(p0.y), w1 = __int_as_float(p1.y);
        float w2 = __int_as_float(p2.y), w3 = __int_as_float(p3.y);
        float2 a0 = __half22float2(*(const __half2*)&r0.x);
        float2 b0 = __half22float2(*(const __half2*)&r0.y);
        float2 a1 = __half22float2(*(const __half2*)&r1.x);
        float2 b1 = __half22float2(*(const __half2*)&r1.y);
        float2 a2 = __half22float2(*(const __half2*)&r2.x);
        float2 b2 = __half22float2(*(const __half2*)&r2.y);
        float2 a3 = __half22float2(*(const __half2*)&r3.x);
        float2 b3 = __half22float2(*(const __half2*)&r3.y);
        acc.x += w0 * a0.x + w1 * a1.x + w2 * a2.x + w3 * a3.x;
        acc.y += w0 * a0.y + w1 * a1.y + w2 * a2.y + w3 * a3.y;
        acc.z += w0 * b0.x + w1 * b1.x + w2 * b2.x + w3 * b3.x;
        acc.w += w0 * b0.y + w1 * b1.y + w2 * b2.y + w3 * b3.y;
    }
    for (; e < end; e++) {
        int2 p = __ldg(&pair[e]);
        uint2 rv = __ldg(xh + (size_t)p.x * 32 + lane);
        float ww = __int_as_float(p.y);
        float2 a = __half22float2(*(const __half2*)&rv.x);
        float2 b = __half22float2(*(const __half2*)&rv.y);
        acc.x += ww * a.x; acc.y += ww * a.y;
        acc.z += ww * b.x; acc.w += ww * b.y;
    }
    float inv = 1.0f / fmaxf((float)(end - beg), 1.0f);
    acc.x *= inv; acc.y *= inv; acc.z *= inv; acc.w *= inv;
    uint2 hp, lp;
    split4h(acc, hp, lp);
    ((uint2*)g_shi[r])[v * 32 + lane] = hp;
    ((uint2*)g_slo[r])[v * 32 + lane] = lp;
}

// ---------------------------------------------------------------------------
// Batched B pre-convert (fp16 hi only): g_Bhi[r][n][k] = fp16(W[k][n])
// ---------------------------------------------------------------------------
__global__ void bconv_kernel(
    const float* __restrict__ Ws0, const float* __restrict__ Wn0,
    const float* __restrict__ Ws1, const float* __restrict__ Wn1,
    const float* __restrict__ Ws2, const float* __restrict__ Wn2)
{
    int r = blockIdx.y;
    const float* Ws = (r == 0) ? Ws0 : ((r == 1) ? Ws1 : Ws2);
    const float* Wn = (r == 0) ? Wn0 : ((r == 1) ? Wn1 : Wn2);
    int k = blockIdx.x;      // 0..255
    int n = threadIdx.x;     // 0..127
    float wv = (k < 128) ? __ldg(&Ws[k * 128 + n]) : __ldg(&Wn[(k - 128) * 128 + n]);
    g_Bhi[r][n * 256 + k] = __float2half_rn(wv);
}

// ---------------------------------------------------------------------------
// PTX helpers
// ---------------------------------------------------------------------------
__device__ __forceinline__ uint32_t smem_u32(const void* p) {
    uint32_t a;
    asm("{ .reg .u64 t; cvta.to.shared.u64 t, %1; cvt.u32.u64 %0, t; }"
        : "=r"(a) : "l"(p));
    return a;
}
#define LDSM_X4(r0, r1, r2, r3, addr) \
    asm volatile("ldmatrix.sync.aligned.m8n8.x4.shared.b16 {%0,%1,%2,%3}, [%4];" \
        : "=r"(r0), "=r"(r1), "=r"(r2), "=r"(r3) : "r"(addr))
#define MMA_F16(d, a, b0, b1) \
    asm volatile("mma.sync.aligned.m16n8k16.row.col.f32.f16.f16.f32 " \
        "{%0,%1,%2,%3}, {%4,%5,%6,%7}, {%8,%9}, {%0,%1,%2,%3};" \
        : "+f"((d)[0]), "+f"((d)[1]), "+f"((d)[2]), "+f"((d)[3]) \
        : "r"((a)[0]), "r"((a)[1]), "r"((a)[2]), "r"((a)[3]), \
          "r"(b0), "r"(b1))
__device__ __forceinline__ void cp_async16(uint32_t saddr, const void* gptr, bool pred) {
    int sz = pred ? 16 : 0;
    asm volatile("cp.async.ca.shared.global [%0], [%1], 16, %2;"
        :: "r"(saddr), "l"(gptr), "r"(sz));
}
#define CP_COMMIT() asm volatile("cp.async.commit_group;" ::: "memory")
#define CP_WAIT1() asm volatile("cp.async.wait_group 1;" ::: "memory")
#define CP_WAIT0() asm volatile("cp.async.wait_group 0;" ::: "memory")

// smem layout (bytes, per stage): Ahi 0, Alo 10240, Bhi 20480
#define ASTR    40          // b16 row stride (80 B)
#define ROWB    80
#define OFF_ALO 10240
#define OFF_BHI 20480
#define STAGEB  30720
#define EPI_STRIDE 68           // fp32 epilogue staging row stride
#define SMEM_DYN 69632          // max(2*STAGEB=61440, 8*32*EPI_STRIDE*4=69632)

// ---------------------------------------------------------------------------
// Fused tensor-core GEMM, grid (782, 3): blockIdx.y = relation.
//   z_r = [x | s_r] @ fp16(W_r) + b_r ;  out += relu(z_r)/3  (atomic f32x4)
// fp16 2-pass: (Ahi + Alo) x Bhi, fp32 accum. CTA 128x128, 8 warps.
// ---------------------------------------------------------------------------
__global__ __launch_bounds__(256, 2) void gemm_mma_kernel(
    const float* __restrict__ b0, const float* __restrict__ b1,
    const float* __restrict__ b2, float* __restrict__ out)
{
    extern __shared__ __align__(16) char dynsmem[];
    uint32_t sbase = smem_u32(dynsmem);

    int r   = blockIdx.y;
    int tid = threadIdx.x;
    int wid = tid >> 5, lid = tid & 31;
    int m0  = blockIdx.x * 128;

    int wm = wid & 3;        // M quadrant
    int wn = wid >> 2;       // N half

    const __half* sHi = g_shi[r];
    const __half* sLo = g_slo[r];
    const __half* BHi = g_Bhi[r];
    const float* bias = (r == 0) ? b0 : ((r == 1) ? b1 : b2);

    float acc[2][8][4];
    #pragma unroll
    for (int i = 0; i < 2; i++)
        #pragma unroll
        for (int j = 0; j < 8; j++)
            #pragma unroll
            for (int q = 0; q < 4; q++) acc[i][j][q] = 0.f;

    // staging indices (constant over chunks)
    int f0 = tid, f1 = tid + 256;
    int row0 = f0 >> 2, q0 = f0 & 3;
    int row1 = f1 >> 2, q1 = f1 & 3;
    bool p0 = (m0 + row0) < NN, p1 = (m0 + row1) < NN;
    size_t aIdx0 = (size_t)(p0 ? (m0 + row0) : 0) * 16 + q0;
    size_t aIdx1 = (size_t)(p1 ? (m0 + row1) : 0) * 16 + q1;
    size_t bIdx0 = (size_t)row0 * 32 + q0;
    size_t bIdx1 = (size_t)row1 * 32 + q1;
    uint32_t sA0 = (uint32_t)(row0 * ROWB + q0 * 16);
    uint32_t sA1 = (uint32_t)(row1 * ROWB + q1 * 16);

    auto stage = [&](int c) {
        uint32_t base = sbase + (uint32_t)(c & 1) * STAGEB;
        const uint4* srcHi = (c < 4) ? (const uint4*)g_xhi : (const uint4*)sHi;
        const uint4* srcLo = (c < 4) ? (const uint4*)g_xlo : (const uint4*)sLo;
        int cc4 = (c & 3) * 4;
        cp_async16(base + sA0,           srcHi + aIdx0 + cc4, p0);
        cp_async16(base + sA1,           srcHi + aIdx1 + cc4, p1);
        cp_async16(base + OFF_ALO + sA0, srcLo + aIdx0 + cc4, p0);
        cp_async16(base + OFF_ALO + sA1, srcLo + aIdx1 + cc4, p1);
        cp_async16(base + OFF_BHI + sA0, (const uint4*)BHi + bIdx0 + c * 4, true);
        cp_async16(base + OFF_BHI + sA1, (const uint4*)BHi + bIdx1 + c * 4, true);
    };

    int aRow = lid & 15;
    int aKof = (lid >> 4) * 8;

    stage(0);
    CP_COMMIT();

    for (int c = 0; c < 8; c++) {
        if (c < 7) { stage(c + 1); CP_COMMIT(); CP_WAIT1(); }
        else       { CP_WAIT0(); }
        __syncthreads();

        uint32_t base = sbase + (uint32_t)(c & 1) * STAGEB;
        uint32_t aHiBase = base, aLoBase = base + OFF_ALO;
        uint32_t bHiBase = base + OFF_BHI;

        #pragma unroll
        for (int ks = 0; ks < 2; ks++) {
            uint32_t ahi[2][4], alo[2][4];
            #pragma unroll
            for (int mt = 0; mt < 2; mt++) {
                uint32_t off = (uint32_t)(((wm * 32 + mt * 16 + aRow) * ASTR
                                           + ks * 16 + aKof) * 2);
                LDSM_X4(ahi[mt][0], ahi[mt][1], ahi[mt][2], ahi[mt][3], aHiBase + off);
                LDSM_X4(alo[mt][0], alo[mt][1], alo[mt][2], alo[mt][3], aLoBase + off);
            }
            #pragma unroll
            for (int np = 0; np < 4; np++) {
                uint32_t bo = (uint32_t)(((wn * 64 + np * 16 + aRow) * ASTR
                                          + ks * 16 + aKof) * 2);
                uint32_t bh[4];
                LDSM_X4(bh[0], bh[1], bh[2], bh[3], bHiBase + bo);
                int nt0 = np * 2, nt1 = np * 2 + 1;
                #pragma unroll
                for (int mt = 0; mt < 2; mt++) {
                    MMA_F16(acc[mt][nt0], ahi[mt], bh[0], bh[2]);
                    MMA_F16(acc[mt][nt0], alo[mt], bh[0], bh[2]);
                    MMA_F16(acc[mt][nt1], ahi[mt], bh[1], bh[3]);
                    MMA_F16(acc[mt][nt1], alo[mt], bh[1], bh[3]);
                }
            }
        }
        __syncthreads();
    }

    // ---- epilogue: bias+relu+1/3 -> warp-private smem tile -> float4 atomicAdd
    const float third = 1.0f / 3.0f;
    int tq = lid >> 2;
    int tr = lid & 3;
    float* wsm = (float*)(dynsmem + wid * (32 * EPI_STRIDE * 4));

    #pragma unroll
    for (int mt = 0; mt < 2; mt++) {
        #pragma unroll
        for (int hf = 0; hf < 2; hf++) {
            int row = mt * 16 + hf * 8 + tq;       // 0..31 (local)
            #pragma unroll
            for (int nt = 0; nt < 8; nt++) {
                int col = nt * 8 + tr * 2;         // 0..63 (local)
                float v0 = acc[mt][nt][hf * 2 + 0] + __ldg(&bias[wn * 64 + col]);
                float v1 = acc[mt][nt][hf * 2 + 1] + __ldg(&bias[wn * 64 + col + 1]);
                v0 = fmaxf(v0, 0.f) * third;
                v1 = fmaxf(v1, 0.f) * third;
                *(float2*)(wsm + row * EPI_STRIDE + col) = make_float2(v0, v1);
            }
        }
    }
    __syncwarp();

    // 32 rows x 16 float4 = 512 float4 per warp -> 16 iterations of 32 lanes
    float4* out4 = (float4*)out;
    #pragma unroll
    for (int i = 0; i < 16; i++) {
        int idx = i * 32 + lid;        // 0..511
        int row = idx >> 4;            // 0..31
        int c4  = idx & 15;            // 0..15
        int rg = m0 + wm * 32 + row;
        if (rg < NN) {
            float4 v = *(const float4*)(wsm + row * EPI_STRIDE + c4 * 4);
            atomicAdd(&out4[(size_t)rg * 32 + wn * 16 + c4], v);
        }
    }
}

// ---------------------------------------------------------------------------
// Launch. Inputs identified BY SIZE (robust to either metadata ordering).
// ---------------------------------------------------------------------------
extern "C" void kernel_launch(void* const* d_in, const int* in_sizes, int n_in,
                              void* d_out, int out_size)
{
    const float* x = nullptr;
    const int*   srcA[3] = {nullptr, nullptr, nullptr};
    const int*   dstA[3] = {nullptr, nullptr, nullptr};
    const float* wA[3]   = {nullptr, nullptr, nullptr};
    const float* WsA[3]  = {nullptr, nullptr, nullptr};
    const float* WnA[3]  = {nullptr, nullptr, nullptr};
    const float* bA[3]   = {nullptr, nullptr, nullptr};

    int nEdge = 0, nMat = 0, nBias = 0;
    for (int i = 0; i < n_in; i++) {
        int sz = in_sizes[i];
        if (sz == NN * DD) {
            x = (const float*)d_in[i];
        } else if (sz == EE) {
            int k = nEdge++;
            int rel = k / 3, kind = k % 3;
            if (rel < 3) {
                if (kind == 0)      srcA[rel] = (const int*)d_in[i];
                else if (kind == 1) dstA[rel] = (const int*)d_in[i];
                else                wA[rel]   = (const float*)d_in[i];
            }
        } else if (sz == DD * HH) {
            int k = nMat++;
            int rel = k / 2;
            if (rel < 3) {
                if ((k & 1) == 0) WsA[rel] = (const float*)d_in[i];
                else              WnA[rel] = (const float*)d_in[i];
            }
        } else if (sz == HH) {
            if (nBias < 3) bA[nBias++] = (const float*)d_in[i];
        }
    }

    float* out = (float*)d_out;

    cudaFuncSetAttribute(gemm_mma_kernel,
                         cudaFuncAttributeMaxDynamicSharedMemorySize, SMEM_DYN);

    dim3 edgeG((EE + 255) / 256, 3);
    dim3 nodeG((NN + 255) / 256, 3);
    dim3 pullG((NN * 32 + 255) / 256, 3);
    dim3 scanRG(SCAN_B, 3);
    dim3 scanPG(1, 3);
    dim3 bconvG(256, 3);
    dim3 gemmG((NN + 127) / 128, 3);
    int xconvBlocks = (NN * 32 + 255) / 256;

    xconv_kernel<<<xconvBlocks, 256>>>(x, out);
    zero_cnt_kernel<<<nodeG, 256>>>();
    hist_kernel<<<edgeG, 256>>>(dstA[0], dstA[1], dstA[2]);
    scan_reduce_kernel<<<scanRG, 1024>>>();
    scan_part_kernel<<<scanPG, 128>>>();
    scan_final_kernel<<<scanRG, 1024>>>();
    fill_kernel<<<edgeG, 256>>>(srcA[0], dstA[0], wA[0],
                                srcA[1], dstA[1], wA[1],
                                srcA[2], dstA[2], wA[2]);
    pull_kernel<<<pullG, 256>>>();
    bconv_kernel<<<bconvG, 128>>>(WsA[0], WnA[0], WsA[1], WnA[1], WsA[2], WnA[2]);
    gemm_mma_kernel<<<gemmG, 256, SMEM_DYN>>>(bA[0], bA[1], bA[2], out);
}

// round 16
// speedup vs baseline: 3.2187x; 1.1922x over previous
#include <cuda_runtime.h>
#include <cuda_fp16.h>
#include <cstdint>

#define NN 100000
#define EE 1600000
#define DD 128
#define HH 128

// ---------------------------------------------------------------------------
// Scratch (per-relation where needed)
// ---------------------------------------------------------------------------
__device__ int    g_cnt[3][NN];
__device__ int    g_rs[3][NN + 1];
__device__ int    g_cur[3][NN];
__device__ int2   g_pair[3][EE];
__device__ int    g_partraw[3][128];
__device__ int    g_part[3][128];
// fp16 operands (single-pass scheme: A and B both plain fp16, fp32 accum)
__device__ __align__(16) __half g_xh[NN * 128];
__device__ __align__(16) __half g_sh[3][NN * 128];
__device__ __align__(16) __half g_Bh[3][128 * 256];   // [n][k]

#define SCAN_B 98          // ceil(NN / 1024)

// ---------------------------------------------------------------------------
// fp16 convert helper (hi only)
// ---------------------------------------------------------------------------
__device__ __forceinline__ uint2 cvt4h(float4 v) {
    __half h0 = __float2half_rn(v.x), h1 = __float2half_rn(v.y);
    __half h2 = __float2half_rn(v.z), h3 = __float2half_rn(v.w);
    uint2 hp;
    hp.x = (uint32_t)__half_as_ushort(h0) | ((uint32_t)__half_as_ushort(h1) << 16);
    hp.y = (uint32_t)__half_as_ushort(h2) | ((uint32_t)__half_as_ushort(h3) << 16);
    return hp;
}

// x -> fp16; also zero-initializes out (same element count).
__global__ void xconv_kernel(const float* __restrict__ x, float* __restrict__ out) {
    int i = blockIdx.x * blockDim.x + threadIdx.x;
    if (i >= NN * 32) return;
    float4 v = __ldg((const float4*)x + i);
    ((uint2*)g_xh)[i] = cvt4h(v);
    ((float4*)out)[i] = make_float4(0.f, 0.f, 0.f, 0.f);
}

// ---------------------------------------------------------------------------
// Batched CSR build (blockIdx.y = relation)
// ---------------------------------------------------------------------------
__global__ void zero_cnt_kernel() {
    int i = blockIdx.x * blockDim.x + threadIdx.x;
    if (i < NN) g_cnt[blockIdx.y][i] = 0;
}

__global__ void hist_kernel(const int* __restrict__ d0, const int* __restrict__ d1,
                            const int* __restrict__ d2) {
    int r = blockIdx.y;
    const int* dst = (r == 0) ? d0 : ((r == 1) ? d1 : d2);
    int e = blockIdx.x * blockDim.x + threadIdx.x;
    if (e < EE) atomicAdd(&g_cnt[r][__ldg(&dst[e])], 1);
}

__global__ void scan_reduce_kernel() {
    int r = blockIdx.y;
    int b = blockIdx.x, t = threadIdx.x;
    int gi = b * 1024 + t;
    int v = (gi < NN) ? g_cnt[r][gi] : 0;
    #pragma unroll
    for (int o = 16; o > 0; o >>= 1) v += __shfl_down_sync(0xFFFFFFFFu, v, o);
    __shared__ int wsum[32];
    int lane = t & 31, wid = t >> 5;
    if (lane == 0) wsum[wid] = v;
    __syncthreads();
    if (wid == 0) {
        int s = wsum[lane];
        #pragma unroll
        for (int o = 16; o > 0; o >>= 1) s += __shfl_down_sync(0xFFFFFFFFu, s, o);
        if (lane == 0) g_partraw[r][b] = s;
    }
}

__global__ void scan_part_kernel() {
    int r = blockIdx.y;
    __shared__ int sm[SCAN_B];
    int t = threadIdx.x;
    if (t < SCAN_B) sm[t] = g_partraw[r][t];
    __syncthreads();
    if (t == 0) {
        int run = 0;
        for (int i = 0; i < SCAN_B; i++) { int c = sm[i]; sm[i] = run; run += c; }
    }
    __syncthreads();
    if (t < SCAN_B) g_part[r][t] = sm[t];
}

__global__ void scan_final_kernel() {
    int r = blockIdx.y;
    int b = blockIdx.x, t = threadIdx.x;
    int gi = b * 1024 + t;
    int lane = t & 31, wid = t >> 5;
    int v = (gi < NN) ? g_cnt[r][gi] : 0;
    int xv = v;
    #pragma unroll
    for (int o = 1; o < 32; o <<= 1) {
        int y = __shfl_up_sync(0xFFFFFFFFu, xv, o);
        if (lane >= o) xv += y;
    }
    __shared__ int wsum[32];
    if (lane == 31) wsum[wid] = xv;
    __syncthreads();
    if (wid == 0) {
        int s = wsum[lane];
        #pragma unroll
        for (int o = 1; o < 32; o <<= 1) {
            int y = __shfl_up_sync(0xFFFFFFFFu, s, o);
            if (lane >= o) s += y;
        }
        wsum[lane] = s;
    }
    __syncthreads();
    int excl = xv - v + ((wid > 0) ? wsum[wid - 1] : 0) + g_part[r][b];
    if (gi < NN) { g_rs[r][gi] = excl; g_cur[r][gi] = excl; }
    if (gi == NN - 1) g_rs[r][NN] = excl + v;
}

__global__ void fill_kernel(
    const int* __restrict__ s0, const int* __restrict__ d0, const float* __restrict__ w0,
    const int* __restrict__ s1, const int* __restrict__ d1, const float* __restrict__ w1,
    const int* __restrict__ s2, const int* __restrict__ d2, const float* __restrict__ w2)
{
    int r = blockIdx.y;
    const int* src = (r == 0) ? s0 : ((r == 1) ? s1 : s2);
    const int* dst = (r == 0) ? d0 : ((r == 1) ? d1 : d2);
    const float* w = (r == 0) ? w0 : ((r == 1) ? w1 : w2);
    int e = blockIdx.x * blockDim.x + threadIdx.x;
    if (e >= EE) return;
    int v = __ldg(&dst[e]);
    int pos = atomicAdd(&g_cur[r][v], 1);
    g_pair[r][pos] = make_int2(__ldg(&src[e]), __float_as_int(__ldg(&w[e])));
}

// ---------------------------------------------------------------------------
// Batched pull: one warp per (node, relation). Gathers fp16 x rows (256 B),
// accumulates fp32, stores pre-normalized fp16.
// ---------------------------------------------------------------------------
__global__ __launch_bounds__(256) void pull_kernel() {
    int r = blockIdx.y;
    int v = (int)((blockIdx.x * blockDim.x + threadIdx.x) >> 5);
    if (v >= NN) return;
    int lane = threadIdx.x & 31;

    int beg = __ldg(&g_rs[r][v]);
    int end = __ldg(&g_rs[r][v + 1]);
    const uint2* xh = (const uint2*)g_xh;   // row = 32 uint2 (4 halves each)
    const int2* pair = g_pair[r];

    float4 acc = make_float4(0.f, 0.f, 0.f, 0.f);
    int e = beg;
    for (; e + 4 <= end; e += 4) {
        int2 p0 = __ldg(&pair[e]);
        int2 p1 = __ldg(&pair[e + 1]);
        int2 p2 = __ldg(&pair[e + 2]);
        int2 p3 = __ldg(&pair[e + 3]);
        uint2 r0 = __ldg(xh + (size_t)p0.x * 32 + lane);
        uint2 r1 = __ldg(xh + (size_t)p1.x * 32 + lane);
        uint2 r2 = __ldg(xh + (size_t)p2.x * 32 + lane);
        uint2 r3 = __ldg(xh + (size_t)p3.x * 32 + lane);
        float w0 = __int_as_float(p0.y), w1 = __int_as_float(p1.y);
        float w2 = __int_as_float(p2.y), w3 = __int_as_float(p3.y);
        float2 a0 = __half22float2(*(const __half2*)&r0.x);
        float2 b0 = __half22float2(*(const __half2*)&r0.y);
        float2 a1 = __half22float2(*(const __half2*)&r1.x);
        float2 b1 = __half22float2(*(const __half2*)&r1.y);
        float2 a2 = __half22float2(*(const __half2*)&r2.x);
        float2 b2 = __half22float2(*(const __half2*)&r2.y);
        float2 a3 = __half22float2(*(const __half2*)&r3.x);
        float2 b3 = __half22float2(*(const __half2*)&r3.y);
        acc.x += w0 * a0.x + w1 * a1.x + w2 * a2.x + w3 * a3.x;
        acc.y += w0 * a0.y + w1 * a1.y + w2 * a2.y + w3 * a3.y;
        acc.z += w0 * b0.x + w1 * b1.x + w2 * b2.x + w3 * b3.x;
        acc.w += w0 * b0.y + w1 * b1.y + w2 * b2.y + w3 * b3.y;
    }
    for (; e < end; e++) {
        int2 p = __ldg(&pair[e]);
        uint2 rv = __ldg(xh + (size_t)p.x * 32 + lane);
        float ww = __int_as_float(p.y);
        float2 a = __half22float2(*(const __half2*)&rv.x);
        float2 b = __half22float2(*(const __half2*)&rv.y);
        acc.x += ww * a.x; acc.y += ww * a.y;
        acc.z += ww * b.x; acc.w += ww * b.y;
    }
    float inv = 1.0f / fmaxf((float)(end - beg), 1.0f);
    acc.x *= inv; acc.y *= inv; acc.z *= inv; acc.w *= inv;
    ((uint2*)g_sh[r])[v * 32 + lane] = cvt4h(acc);
}

// ---------------------------------------------------------------------------
// Batched B pre-convert: g_Bh[r][n][k] = fp16(W[k][n])
// ---------------------------------------------------------------------------
__global__ void bconv_kernel(
    const float* __restrict__ Ws0, const float* __restrict__ Wn0,
    const float* __restrict__ Ws1, const float* __restrict__ Wn1,
    const float* __restrict__ Ws2, const float* __restrict__ Wn2)
{
    int r = blockIdx.y;
    const float* Ws = (r == 0) ? Ws0 : ((r == 1) ? Ws1 : Ws2);
    const float* Wn = (r == 0) ? Wn0 : ((r == 1) ? Wn1 : Wn2);
    int k = blockIdx.x;      // 0..255
    int n = threadIdx.x;     // 0..127
    float wv = (k < 128) ? __ldg(&Ws[k * 128 + n]) : __ldg(&Wn[(k - 128) * 128 + n]);
    g_Bh[r][n * 256 + k] = __float2half_rn(wv);
}

// ---------------------------------------------------------------------------
// PTX helpers
// ---------------------------------------------------------------------------
__device__ __forceinline__ uint32_t smem_u32(const void* p) {
    uint32_t a;
    asm("{ .reg .u64 t; cvta.to.shared.u64 t, %1; cvt.u32.u64 %0, t; }"
        : "=r"(a) : "l"(p));
    return a;
}
#define LDSM_X4(r0, r1, r2, r3, addr) \
    asm volatile("ldmatrix.sync.aligned.m8n8.x4.shared.b16 {%0,%1,%2,%3}, [%4];" \
        : "=r"(r0), "=r"(r1), "=r"(r2), "=r"(r3) : "r"(addr))
#define MMA_F16(d, a, b0, b1) \
    asm volatile("mma.sync.aligned.m16n8k16.row.col.f32.f16.f16.f32 " \
        "{%0,%1,%2,%3}, {%4,%5,%6,%7}, {%8,%9}, {%0,%1,%2,%3};" \
        : "+f"((d)[0]), "+f"((d)[1]), "+f"((d)[2]), "+f"((d)[3]) \
        : "r"((a)[0]), "r"((a)[1]), "r"((a)[2]), "r"((a)[3]), \
          "r"(b0), "r"(b1))
__device__ __forceinline__ void cp_async16(uint32_t saddr, const void* gptr, bool pred) {
    int sz = pred ? 16 : 0;
    asm volatile("cp.async.ca.shared.global [%0], [%1], 16, %2;"
        :: "r"(saddr), "l"(gptr), "r"(sz));
}
#define CP_COMMIT() asm volatile("cp.async.commit_group;" ::: "memory")
#define CP_WAIT1() asm volatile("cp.async.wait_group 1;" ::: "memory")
#define CP_WAIT0() asm volatile("cp.async.wait_group 0;" ::: "memory")

// smem layout (bytes, per stage): Ah 0, Bh 10240
#define ASTR    40          // b16 row stride (80 B)
#define ROWB    80
#define OFF_BH  10240
#define STAGEB  20480
#define EPI_STRIDE 68           // fp32 epilogue staging row stride
#define SMEM_DYN 69632          // max(2*STAGEB=40960, 8*32*EPI_STRIDE*4=69632)

// ---------------------------------------------------------------------------
// Fused tensor-core GEMM, grid (782, 3): blockIdx.y = relation.
//   z_r = fp16([x | s_r]) @ fp16(W_r) + b_r ;  out += relu(z_r)/3 (atomic f32x4)
// Single-pass fp16, fp32 accum. CTA 128x128, 8 warps (4M x 2N).
// ---------------------------------------------------------------------------
__global__ __launch_bounds__(256, 2) void gemm_mma_kernel(
    const float* __restrict__ b0, const float* __restrict__ b1,
    const float* __restrict__ b2, float* __restrict__ out)
{
    extern __shared__ __align__(16) char dynsmem[];
    uint32_t sbase = smem_u32(dynsmem);

    int r   = blockIdx.y;
    int tid = threadIdx.x;
    int wid = tid >> 5, lid = tid & 31;
    int m0  = blockIdx.x * 128;

    int wm = wid & 3;        // M quadrant
    int wn = wid >> 2;       // N half

    const __half* sH = g_sh[r];
    const __half* BH = g_Bh[r];
    const float* bias = (r == 0) ? b0 : ((r == 1) ? b1 : b2);

    float acc[2][8][4];
    #pragma unroll
    for (int i = 0; i < 2; i++)
        #pragma unroll
        for (int j = 0; j < 8; j++)
            #pragma unroll
            for (int q = 0; q < 4; q++) acc[i][j][q] = 0.f;

    // staging indices (constant over chunks)
    int f0 = tid, f1 = tid + 256;
    int row0 = f0 >> 2, q0 = f0 & 3;
    int row1 = f1 >> 2, q1 = f1 & 3;
    bool p0 = (m0 + row0) < NN, p1 = (m0 + row1) < NN;
    size_t aIdx0 = (size_t)(p0 ? (m0 + row0) : 0) * 16 + q0;
    size_t aIdx1 = (size_t)(p1 ? (m0 + row1) : 0) * 16 + q1;
    size_t bIdx0 = (size_t)row0 * 32 + q0;
    size_t bIdx1 = (size_t)row1 * 32 + q1;
    uint32_t sA0 = (uint32_t)(row0 * ROWB + q0 * 16);
    uint32_t sA1 = (uint32_t)(row1 * ROWB + q1 * 16);

    auto stage = [&](int c) {
        uint32_t base = sbase + (uint32_t)(c & 1) * STAGEB;
        const uint4* srcA = (c < 4) ? (const uint4*)g_xh : (const uint4*)sH;
        int cc4 = (c & 3) * 4;
        cp_async16(base + sA0,          srcA + aIdx0 + cc4, p0);
        cp_async16(base + sA1,          srcA + aIdx1 + cc4, p1);
        cp_async16(base + OFF_BH + sA0, (const uint4*)BH + bIdx0 + c * 4, true);
        cp_async16(base + OFF_BH + sA1, (const uint4*)BH + bIdx1 + c * 4, true);
    };

    int aRow = lid & 15;
    int aKof = (lid >> 4) * 8;

    stage(0);
    CP_COMMIT();

    for (int c = 0; c < 8; c++) {
        if (c < 7) { stage(c + 1); CP_COMMIT(); CP_WAIT1(); }
        else       { CP_WAIT0(); }
        __syncthreads();

        uint32_t base = sbase + (uint32_t)(c & 1) * STAGEB;
        uint32_t aBase = base, bBase = base + OFF_BH;

        #pragma unroll
        for (int ks = 0; ks < 2; ks++) {
            uint32_t ah[2][4];
            #pragma unroll
            for (int mt = 0; mt < 2; mt++) {
                uint32_t off = (uint32_t)(((wm * 32 + mt * 16 + aRow) * ASTR
                                           + ks * 16 + aKof) * 2);
                LDSM_X4(ah[mt][0], ah[mt][1], ah[mt][2], ah[mt][3], aBase + off);
            }
            #pragma unroll
            for (int np = 0; np < 4; np++) {
                uint32_t bo = (uint32_t)(((wn * 64 + np * 16 + aRow) * ASTR
                                          + ks * 16 + aKof) * 2);
                uint32_t bh[4];
                LDSM_X4(bh[0], bh[1], bh[2], bh[3], bBase + bo);
                int nt0 = np * 2, nt1 = np * 2 + 1;
                #pragma unroll
                for (int mt = 0; mt < 2; mt++) {
                    MMA_F16(acc[mt][nt0], ah[mt], bh[0], bh[2]);
                    MMA_F16(acc[mt][nt1], ah[mt], bh[1], bh[3]);
                }
            }
        }
        __syncthreads();
    }

    // ---- epilogue: bias+relu+1/3 -> warp-private smem tile -> float4 atomicAdd
    const float third = 1.0f / 3.0f;
    int tq = lid >> 2;
    int tr = lid & 3;
    float* wsm = (float*)(dynsmem + wid * (32 * EPI_STRIDE * 4));

    #pragma unroll
    for (int mt = 0; mt < 2; mt++) {
        #pragma unroll
        for (int hf = 0; hf < 2; hf++) {
            int row = mt * 16 + hf * 8 + tq;       // 0..31 (local)
            #pragma unroll
            for (int nt = 0; nt < 8; nt++) {
                int col = nt * 8 + tr * 2;         // 0..63 (local)
                float v0 = acc[mt][nt][hf * 2 + 0] + __ldg(&bias[wn * 64 + col]);
                float v1 = acc[mt][nt][hf * 2 + 1] + __ldg(&bias[wn * 64 + col + 1]);
                v0 = fmaxf(v0, 0.f) * third;
                v1 = fmaxf(v1, 0.f) * third;
                *(float2*)(wsm + row * EPI_STRIDE + col) = make_float2(v0, v1);
            }
        }
    }
    __syncwarp();

    // 32 rows x 16 float4 = 512 float4 per warp -> 16 iterations of 32 lanes
    float4* out4 = (float4*)out;
    #pragma unroll
    for (int i = 0; i < 16; i++) {
        int idx = i * 32 + lid;        // 0..511
        int row = idx >> 4;            // 0..31
        int c4  = idx & 15;            // 0..15
        int rg = m0 + wm * 32 + row;
        if (rg < NN) {
            float4 v = *(const float4*)(wsm + row * EPI_STRIDE + c4 * 4);
            atomicAdd(&out4[(size_t)rg * 32 + wn * 16 + c4], v);
        }
    }
}

// ---------------------------------------------------------------------------
// Launch. Inputs identified BY SIZE (robust to either metadata ordering).
// ---------------------------------------------------------------------------
extern "C" void kernel_launch(void* const* d_in, const int* in_sizes, int n_in,
                              void* d_out, int out_size)
{
    const float* x = nullptr;
    const int*   srcA[3] = {nullptr, nullptr, nullptr};
    const int*   dstA[3] = {nullptr, nullptr, nullptr};
    const float* wA[3]   = {nullptr, nullptr, nullptr};
    const float* WsA[3]  = {nullptr, nullptr, nullptr};
    const float* WnA[3]  = {nullptr, nullptr, nullptr};
    const float* bA[3]   = {nullptr, nullptr, nullptr};

    int nEdge = 0, nMat = 0, nBias = 0;
    for (int i = 0; i < n_in; i++) {
        int sz = in_sizes[i];
        if (sz == NN * DD) {
            x = (const float*)d_in[i];
        } else if (sz == EE) {
            int k = nEdge++;
            int rel = k / 3, kind = k % 3;
            if (rel < 3) {
                if (kind == 0)      srcA[rel] = (const int*)d_in[i];
                else if (kind == 1) dstA[rel] = (const int*)d_in[i];
                else                wA[rel]   = (const float*)d_in[i];
            }
        } else if (sz == DD * HH) {
            int k = nMat++;
            int rel = k / 2;
            if (rel < 3) {
                if ((k & 1) == 0) WsA[rel] = (const float*)d_in[i];
                else              WnA[rel] = (const float*)d_in[i];
            }
        } else if (sz == HH) {
            if (nBias < 3) bA[nBias++] = (const float*)d_in[i];
        }
    }

    float* out = (float*)d_out;

    cudaFuncSetAttribute(gemm_mma_kernel,
                         cudaFuncAttributeMaxDynamicSharedMemorySize, SMEM_DYN);

    dim3 edgeG((EE + 255) / 256, 3);
    dim3 nodeG((NN + 255) / 256, 3);
    dim3 pullG((NN * 32 + 255) / 256, 3);
    dim3 scanRG(SCAN_B, 3);
    dim3 scanPG(1, 3);
    dim3 bconvG(256, 3);
    dim3 gemmG((NN + 127) / 128, 3);
    int xconvBlocks = (NN * 32 + 255) / 256;

    xconv_kernel<<<xconvBlocks, 256>>>(x, out);
    zero_cnt_kernel<<<nodeG, 256>>>();
    hist_kernel<<<edgeG, 256>>>(dstA[0], dstA[1], dstA[2]);
    scan_reduce_kernel<<<scanRG, 1024>>>();
    scan_part_kernel<<<scanPG, 128>>>();
    scan_final_kernel<<<scanRG, 1024>>>();
    fill_kernel<<<edgeG, 256>>>(srcA[0], dstA[0], wA[0],
                                srcA[1], dstA[1], wA[1],
                                srcA[2], dstA[2], wA[2]);
    pull_kernel<<<pullG, 256>>>();
    bconv_kernel<<<bconvG, 128>>>(WsA[0], WnA[0], WsA[1], WnA[1], WsA[2], WnA[2]);
    gemm_mma_kernel<<<gemmG, 256, SMEM_DYN>>>(bA[0], bA[1], bA[2], out);
}